// round 1
// baseline (speedup 1.0000x reference)
#include <cuda_runtime.h>
#include <cuda_bf16.h>
#include <cstddef>

#define B_  4
#define T_  2048
#define C_  1024
#define H_  16
#define HS  64
#define BT  (B_ * T_)        // 8192
#define FF  (4 * C_)         // 4096

// ---------------- scratch (device globals; no allocation allowed) ----------
__device__ float g_xn [BT * C_];   // ln1(x)
__device__ float g_q  [BT * C_];   // [B,H,T,hs]
__device__ float g_k  [BT * C_];
__device__ float g_v  [BT * C_];
__device__ float g_att[BT * C_];   // attention out, [B,T,C]
__device__ float g_x1 [BT * C_];   // x + attn @ Wo + bo
__device__ float g_xn2[BT * C_];   // ln2(x1)
__device__ float g_h  [BT * FF];   // relu(xn2 @ W1 + b1)

// ---------------- LayerNorm: one block per row, 256 thr, C=1024 ----------
__global__ void ln_kernel(const float* __restrict__ x,
                          const float* __restrict__ g,
                          const float* __restrict__ b,
                          float* __restrict__ out) {
    int row = blockIdx.x;
    int tid = threadIdx.x;                       // 0..255
    const float4* xr = (const float4*)(x + (size_t)row * C_);
    float4 xv = xr[tid];
    float s  = xv.x + xv.y + xv.z + xv.w;
    float ss = xv.x * xv.x + xv.y * xv.y + xv.z * xv.z + xv.w * xv.w;
    #pragma unroll
    for (int o = 16; o > 0; o >>= 1) {
        s  += __shfl_xor_sync(0xffffffffu, s,  o);
        ss += __shfl_xor_sync(0xffffffffu, ss, o);
    }
    __shared__ float sb[8], sb2[8];
    int wid = tid >> 5, lid = tid & 31;
    if (lid == 0) { sb[wid] = s; sb2[wid] = ss; }
    __syncthreads();
    float tot = 0.f, tot2 = 0.f;
    #pragma unroll
    for (int i = 0; i < 8; i++) { tot += sb[i]; tot2 += sb2[i]; }
    float mean = tot * (1.0f / C_);
    float var  = tot2 * (1.0f / C_) - mean * mean;
    float rstd = rsqrtf(var + 1e-5f);
    float4 gv = ((const float4*)g)[tid];
    float4 bv = ((const float4*)b)[tid];
    float4 ov;
    ov.x = (xv.x - mean) * rstd * gv.x + bv.x;
    ov.y = (xv.y - mean) * rstd * gv.y + bv.y;
    ov.z = (xv.z - mean) * rstd * gv.z + bv.z;
    ov.w = (xv.w - mean) * rstd * gv.w + bv.w;
    ((float4*)(out + (size_t)row * C_))[tid] = ov;
}

// ---------------- SGEMM 128x128x16, 256 threads, 8x8 micro-tile ----------
// BLAY: 0 = B row-major [K,N];  1 = per-head weights [H, C, hs] with N = H*hs
// OLAY: 0 = C row-major [M,N];  1 = scatter to [B,H,T,hs] (q/k/v)
// EPI : 0 = none; 1 = +bias +residual; 2 = relu(+bias)
template<int BLAY>
__device__ __forceinline__ float4 load_b4(const float* __restrict__ Bm,
                                          int kk, int nn, int N) {
    if (BLAY == 0) {
        return *(const float4*)&Bm[(size_t)kk * N + nn];
    } else {
        int h = nn >> 6, d = nn & 63;
        return *(const float4*)&Bm[((size_t)h * C_ + kk) * HS + d];
    }
}

template<int BLAY, int OLAY, int EPI>
__global__ __launch_bounds__(256)
void gemm_kernel(const float* __restrict__ A,
                 const float* __restrict__ Bm,
                 const float* __restrict__ bias,
                 const float* __restrict__ res,
                 float* __restrict__ Cm,
                 int M, int N, int K) {
    constexpr int BK = 16;
    __shared__ float As[BK][128];
    __shared__ float Bs[BK][128];
    const int tid = threadIdx.x;
    const int bm = blockIdx.y * 128;
    const int bn = blockIdx.x * 128;
    const int tx = tid & 15;         // 0..15 -> col group
    const int ty = tid >> 4;         // 0..15 -> row group

    float acc[8][8];
    #pragma unroll
    for (int i = 0; i < 8; i++)
        #pragma unroll
        for (int j = 0; j < 8; j++) acc[i][j] = 0.f;

    const int arow = tid >> 2;        // 0..63 (two rows: arow, arow+64)
    const int acol = (tid & 3) * 4;   // 0,4,8,12
    const int brow = tid >> 5;        // 0..7 (two rows: brow, brow+8)
    const int bcol = (tid & 31) * 4;  // 0..124

    for (int k0 = 0; k0 < K; k0 += BK) {
        #pragma unroll
        for (int r = 0; r < 2; r++) {
            float4 a = *(const float4*)&A[(size_t)(bm + arow + r * 64) * K + k0 + acol];
            As[acol + 0][arow + r * 64] = a.x;
            As[acol + 1][arow + r * 64] = a.y;
            As[acol + 2][arow + r * 64] = a.z;
            As[acol + 3][arow + r * 64] = a.w;
        }
        #pragma unroll
        for (int r = 0; r < 2; r++) {
            float4 bv = load_b4<BLAY>(Bm, k0 + brow + r * 8, bn + bcol, N);
            *(float4*)&Bs[brow + r * 8][bcol] = bv;
        }
        __syncthreads();
        #pragma unroll
        for (int kk = 0; kk < BK; kk++) {
            float af[8], bf[8];
            #pragma unroll
            for (int i = 0; i < 8; i += 4) {
                float4 t = *(const float4*)&As[kk][ty * 8 + i];
                af[i] = t.x; af[i + 1] = t.y; af[i + 2] = t.z; af[i + 3] = t.w;
            }
            #pragma unroll
            for (int j = 0; j < 8; j += 4) {
                float4 t = *(const float4*)&Bs[kk][tx * 8 + j];
                bf[j] = t.x; bf[j + 1] = t.y; bf[j + 2] = t.z; bf[j + 3] = t.w;
            }
            #pragma unroll
            for (int i = 0; i < 8; i++)
                #pragma unroll
                for (int j = 0; j < 8; j++)
                    acc[i][j] += af[i] * bf[j];
        }
        __syncthreads();
    }

    // ---- epilogue ----
    #pragma unroll
    for (int i = 0; i < 8; i++) {
        const int mrow = bm + ty * 8 + i;
        #pragma unroll
        for (int j = 0; j < 8; j += 4) {
            const int n = bn + tx * 8 + j;
            float4 v4 = make_float4(acc[i][j], acc[i][j + 1], acc[i][j + 2], acc[i][j + 3]);
            if (EPI >= 1) {
                float4 bb = *(const float4*)&bias[n];
                v4.x += bb.x; v4.y += bb.y; v4.z += bb.z; v4.w += bb.w;
            }
            if (EPI == 1) {
                float4 rr = *(const float4*)&res[(size_t)mrow * N + n];
                v4.x += rr.x; v4.y += rr.y; v4.z += rr.z; v4.w += rr.w;
            }
            if (EPI == 2) {
                v4.x = fmaxf(v4.x, 0.f); v4.y = fmaxf(v4.y, 0.f);
                v4.z = fmaxf(v4.z, 0.f); v4.w = fmaxf(v4.w, 0.f);
            }
            if (OLAY == 0) {
                *(float4*)&Cm[(size_t)mrow * N + n] = v4;
            } else {
                // scatter to [B,H,T,hs]
                int b = mrow / T_, t = mrow % T_;
                int h = n >> 6, d = n & 63;
                *(float4*)&Cm[(((size_t)b * H_ + h) * T_ + t) * HS + d] = v4;
            }
        }
    }
}

// ---------------- causal flash attention: 1 query/thread, 64-key tiles ----
__global__ __launch_bounds__(128)
void attn_kernel(const float* __restrict__ Q,
                 const float* __restrict__ Kt,
                 const float* __restrict__ Vt,
                 float* __restrict__ out) {
    const int bh  = blockIdx.y;            // b*H + h
    const int q0  = blockIdx.x * 128;
    const int tid = threadIdx.x;           // 128 threads
    const int iq  = q0 + tid;

    __shared__ float Ks[64][HS];
    __shared__ float Vs[64][HS];

    const float* qp = Q + ((size_t)bh * T_ + iq) * HS;
    float qreg[HS], o[HS];
    #pragma unroll
    for (int d = 0; d < HS; d += 4) {
        float4 t = *(const float4*)&qp[d];
        qreg[d] = t.x * 0.125f; qreg[d + 1] = t.y * 0.125f;
        qreg[d + 2] = t.z * 0.125f; qreg[d + 3] = t.w * 0.125f;
    }
    #pragma unroll
    for (int d = 0; d < HS; d++) o[d] = 0.f;
    float m = -1e30f, l = 0.f;

    const int kend = q0 + 128;
    for (int k0 = 0; k0 < kend; k0 += 64) {
        const float4* kp = (const float4*)(Kt + ((size_t)bh * T_ + k0) * HS);
        const float4* vp = (const float4*)(Vt + ((size_t)bh * T_ + k0) * HS);
        __syncthreads();
        #pragma unroll
        for (int r = 0; r < 8; r++) {
            int idx = r * 128 + tid;        // 1024 float4s per tile
            ((float4*)Ks)[idx] = kp[idx];
            ((float4*)Vs)[idx] = vp[idx];
        }
        __syncthreads();
        #pragma unroll
        for (int s = 0; s < 4; s++) {
            float p[16];
            float mx = m;
            #pragma unroll
            for (int j = 0; j < 16; j++) {
                const int kj = s * 16 + j;
                float a = 0.f;
                #pragma unroll
                for (int d = 0; d < HS; d++) a += qreg[d] * Ks[kj][d];
                p[j] = (k0 + kj <= iq) ? a : -1e30f;
                mx = fmaxf(mx, p[j]);
            }
            const float corr = __expf(m - mx);
            m = mx;
            l *= corr;
            #pragma unroll
            for (int d = 0; d < HS; d++) o[d] *= corr;
            #pragma unroll
            for (int j = 0; j < 16; j++) {
                const float pe = __expf(p[j] - mx);
                l += pe;
                #pragma unroll
                for (int d = 0; d < HS; d++) o[d] += pe * Vs[s * 16 + j][d];
            }
        }
    }
    const int b = bh / H_, h = bh % H_;
    const float inv = 1.0f / l;
    float* op = out + ((size_t)(b * T_ + iq)) * C_ + h * HS;
    #pragma unroll
    for (int d = 0; d < HS; d += 4) {
        float4 t = make_float4(o[d] * inv, o[d + 1] * inv, o[d + 2] * inv, o[d + 3] * inv);
        *(float4*)&op[d] = t;
    }
}

// ---------------------------------------------------------------------------
extern "C" void kernel_launch(void* const* d_in, const int* in_sizes, int n_in,
                              void* d_out, int out_size) {
    const float* x   = (const float*)d_in[0];
    const float* Wq  = (const float*)d_in[1];
    const float* Wk  = (const float*)d_in[2];
    const float* Wv  = (const float*)d_in[3];
    const float* Wo  = (const float*)d_in[4];
    const float* bo  = (const float*)d_in[5];
    const float* g1  = (const float*)d_in[6];
    const float* be1 = (const float*)d_in[7];
    const float* g2  = (const float*)d_in[8];
    const float* be2 = (const float*)d_in[9];
    const float* W1  = (const float*)d_in[10];
    const float* b1  = (const float*)d_in[11];
    const float* W2  = (const float*)d_in[12];
    const float* b2  = (const float*)d_in[13];
    float* out = (float*)d_out;

    float *xn, *q, *k, *v, *att, *x1, *xn2, *h;
    cudaGetSymbolAddress((void**)&xn,  g_xn);
    cudaGetSymbolAddress((void**)&q,   g_q);
    cudaGetSymbolAddress((void**)&k,   g_k);
    cudaGetSymbolAddress((void**)&v,   g_v);
    cudaGetSymbolAddress((void**)&att, g_att);
    cudaGetSymbolAddress((void**)&x1,  g_x1);
    cudaGetSymbolAddress((void**)&xn2, g_xn2);
    cudaGetSymbolAddress((void**)&h,   g_h);

    // 1) ln1
    ln_kernel<<<BT, 256>>>(x, g1, be1, xn);
    // 2) q,k,v projections (per-head weight layout, scatter to [B,H,T,hs])
    dim3 gq(C_ / 128, BT / 128);
    gemm_kernel<1, 1, 0><<<gq, 256>>>(xn, Wq, nullptr, nullptr, q, BT, C_, C_);
    gemm_kernel<1, 1, 0><<<gq, 256>>>(xn, Wk, nullptr, nullptr, k, BT, C_, C_);
    gemm_kernel<1, 1, 0><<<gq, 256>>>(xn, Wv, nullptr, nullptr, v, BT, C_, C_);
    // 3) causal attention -> [B,T,C]
    attn_kernel<<<dim3(T_ / 128, B_ * H_), 128>>>(q, k, v, att);
    // 4) x1 = x + att @ Wo + bo
    gemm_kernel<0, 0, 1><<<dim3(C_ / 128, BT / 128), 256>>>(att, Wo, bo, x, x1, BT, C_, C_);
    // 5) ln2
    ln_kernel<<<BT, 256>>>(x1, g2, be2, xn2);
    // 6) h = relu(xn2 @ W1 + b1)
    gemm_kernel<0, 0, 2><<<dim3(FF / 128, BT / 128), 256>>>(xn2, W1, b1, nullptr, h, BT, FF, C_);
    // 7) out = x1 + h @ W2 + b2
    gemm_kernel<0, 0, 1><<<dim3(C_ / 128, BT / 128), 256>>>(h, W2, b2, x1, out, BT, C_, FF);
}

// round 4
// speedup vs baseline: 1.7311x; 1.7311x over previous
#include <cuda_runtime.h>
#include <cuda_bf16.h>
#include <cstdint>
#include <cstddef>

#define B_  4
#define T_  2048
#define C_  1024
#define H_  16
#define HS  64
#define BT  (B_ * T_)        // 8192
#define FF  (4 * C_)         // 4096

// ======================= helpers ===========================================
__device__ __forceinline__ float tf32r(float x) {
    uint32_t u;
    asm("cvt.rna.tf32.f32 %0, %1;" : "=r"(u) : "f"(x));
    return __uint_as_float(u);
}
__device__ __forceinline__ uint32_t smem_u32(const void* p) {
    uint32_t a;
    asm("{ .reg .u64 t; cvta.to.shared.u64 t, %1; cvt.u32.u64 %0, t; }" : "=r"(a) : "l"(p));
    return a;
}
__device__ __forceinline__ void cp16(uint32_t dst, const void* src) {
    asm volatile("cp.async.cg.shared.global [%0], [%1], 16;" :: "r"(dst), "l"(src));
}
#define CP_COMMIT() asm volatile("cp.async.commit_group;" ::: "memory")
#define CP_WAIT1()  asm volatile("cp.async.wait_group 1;" ::: "memory")

__device__ __forceinline__ void mma_tf32(float* d, const uint32_t* a, const uint32_t* b) {
    asm volatile(
        "mma.sync.aligned.m16n8k8.row.col.f32.tf32.tf32.f32 "
        "{%0,%1,%2,%3}, {%4,%5,%6,%7}, {%8,%9}, {%0,%1,%2,%3};"
        : "+f"(d[0]), "+f"(d[1]), "+f"(d[2]), "+f"(d[3])
        : "r"(a[0]), "r"(a[1]), "r"(a[2]), "r"(a[3]), "r"(b[0]), "r"(b[1]));
}

// ======================= scratch ===========================================
__device__ float g_xn  [BT * C_];          // ln1(x), tf32-rounded
__device__ float g_qkv [3 * BT * C_];      // [3][B][H][T][hs]
__device__ float g_att [BT * C_];          // attention out [B,T,C], rounded
__device__ float g_x1  [BT * C_];          // fp32 residual stream
__device__ float g_xn2 [BT * C_];          // ln2(x1), rounded
__device__ float g_h   [BT * FF];          // relu(ff1), rounded
__device__ float g_wqkv[C_ * 3 * C_];      // [K=1024][N=3072] row-major, rounded
__device__ float g_wo  [C_ * C_];          // rounded copies, original [K][N] layout
__device__ float g_w1  [C_ * FF];
__device__ float g_w2  [FF * C_];

// ======================= weight prep =======================================
// pack per-head Wq/Wk/Wv [H,C,hs] -> [C, 3072] row-major (+ tf32 round)
__global__ void pack_qkv_kernel(const float* __restrict__ Wq,
                                const float* __restrict__ Wk,
                                const float* __restrict__ Wv,
                                float* __restrict__ out) {
    int idx = blockIdx.x * blockDim.x + threadIdx.x;   // over float4s
    int n4row = 3 * C_ / 4;                             // 768
    int k = idx / n4row;
    int n = (idx - k * n4row) * 4;
    int which = n >> 10, h = (n >> 6) & 15, d = n & 63;
    const float* W = (which == 0) ? Wq : (which == 1) ? Wk : Wv;
    float4 v = *(const float4*)&W[((size_t)h * C_ + k) * HS + d];
    v.x = tf32r(v.x); v.y = tf32r(v.y); v.z = tf32r(v.z); v.w = tf32r(v.w);
    *(float4*)&out[(size_t)k * (3 * C_) + n] = v;
}

__global__ void round_copy_kernel(const float* __restrict__ in, float* __restrict__ out) {
    int idx = blockIdx.x * blockDim.x + threadIdx.x;
    float4 v = ((const float4*)in)[idx];
    v.x = tf32r(v.x); v.y = tf32r(v.y); v.z = tf32r(v.z); v.w = tf32r(v.w);
    ((float4*)out)[idx] = v;
}

// ======================= LayerNorm =========================================
__global__ void ln_kernel(const float* __restrict__ x,
                          const float* __restrict__ g,
                          const float* __restrict__ b,
                          float* __restrict__ out) {
    int row = blockIdx.x;
    int tid = threadIdx.x;
    const float4* xr = (const float4*)(x + (size_t)row * C_);
    float4 xv = xr[tid];
    float s  = xv.x + xv.y + xv.z + xv.w;
    float ss = xv.x * xv.x + xv.y * xv.y + xv.z * xv.z + xv.w * xv.w;
    #pragma unroll
    for (int o = 16; o > 0; o >>= 1) {
        s  += __shfl_xor_sync(0xffffffffu, s,  o);
        ss += __shfl_xor_sync(0xffffffffu, ss, o);
    }
    __shared__ float sb[8], sb2[8];
    int wid = tid >> 5, lid = tid & 31;
    if (lid == 0) { sb[wid] = s; sb2[wid] = ss; }
    __syncthreads();
    float tot = 0.f, tot2 = 0.f;
    #pragma unroll
    for (int i = 0; i < 8; i++) { tot += sb[i]; tot2 += sb2[i]; }
    float mean = tot * (1.0f / C_);
    float var  = tot2 * (1.0f / C_) - mean * mean;
    float rstd = rsqrtf(var + 1e-5f);
    float4 gv = ((const float4*)g)[tid];
    float4 bv = ((const float4*)b)[tid];
    float4 ov;
    ov.x = tf32r((xv.x - mean) * rstd * gv.x + bv.x);
    ov.y = tf32r((xv.y - mean) * rstd * gv.y + bv.y);
    ov.z = tf32r((xv.z - mean) * rstd * gv.z + bv.z);
    ov.w = tf32r((xv.w - mean) * rstd * gv.w + bv.w);
    ((float4*)(out + (size_t)row * C_))[tid] = ov;
}

// ======================= TF32 mma.sync GEMM ================================
// C[M,N] = A[M,K] @ B[K,N], A row-major, B row-major, both tf32-rounded.
// CTA 128x128, BK=32, 256 thr (8 warps, 4Mx2N, warp tile 32x64), 3-stage cp.async.
// EPI: 0 = scatter to qkv [3][B][H][T][hs]; 1 = +bias +res; 2 = relu(+bias), round.
static constexpr int APAD = 36;    // floats per A smem row (32 + 4)
static constexpr int BPAD = 136;   // floats per B smem row (128 + 8)
static constexpr int ABYTES = 128 * APAD * 4;   // 18432
static constexpr int BBYTES = 32 * BPAD * 4;    // 17408
static constexpr int STAGE_BYTES = ABYTES + BBYTES;  // 35840
static constexpr int NSTAGES = 3;
static constexpr int MM_SMEM = NSTAGES * STAGE_BYTES; // 107520

template<int EPI>
__global__ __launch_bounds__(256)
void mm_kernel(const float* __restrict__ A, const float* __restrict__ Bw,
               const float* __restrict__ bias, const float* __restrict__ res,
               float* __restrict__ Cout, int K, int N) {
    extern __shared__ __align__(16) char dsm[];
    const uint32_t smem0 = smem_u32(dsm);
    const int tid  = threadIdx.x;
    const int wid  = tid >> 5;
    const int lane = tid & 31;
    const int m0 = blockIdx.y * 128;
    const int n0 = blockIdx.x * 128;
    const int nch = K >> 5;

    const int warpM = wid >> 1;           // 0..3
    const int warpN = wid & 1;            // 0..1

    // loader indices
    const int arow[4] = { tid >> 3, (tid + 256) >> 3, (tid + 512) >> 3, (tid + 768) >> 3 };
    const int acb  = (tid & 7) << 4;      // byte offset within A row (0..112)
    const int brow = tid >> 3;            // 0..31
    const int bc0  = (tid & 7) << 4;      // first of 4 B chunks per row

    float acc[2][8][4];
    #pragma unroll
    for (int mt = 0; mt < 2; mt++)
        #pragma unroll
        for (int nt = 0; nt < 8; nt++)
            #pragma unroll
            for (int r = 0; r < 4; r++) acc[mt][nt][r] = 0.f;

    auto load_stage = [&](int st, int kpos) {
        uint32_t sa = smem0 + st * STAGE_BYTES;
        uint32_t sbm = sa + ABYTES;
        #pragma unroll
        for (int j = 0; j < 4; j++) {
            int r = arow[j];
            cp16(sa + r * (APAD * 4) + acb,
                 A + (size_t)(m0 + r) * K + kpos + (acb >> 2));
        }
        const float* brp = Bw + (size_t)(kpos + brow) * N + n0;
        #pragma unroll
        for (int j = 0; j < 4; j++) {
            int cb = bc0 + j * 128;                 // byte offsets 0..496
            cp16(sbm + brow * (BPAD * 4) + cb, brp + (cb >> 2));
        }
    };

    // prologue: stages 0,1
    load_stage(0, 0); CP_COMMIT();
    load_stage(1, 32); CP_COMMIT();

    const int fr = lane >> 2;      // 0..7
    const int fc = lane & 3;       // 0..3

    for (int kc = 0; kc < nch; kc++) {
        CP_WAIT1();
        __syncthreads();
        if (kc + 2 < nch) load_stage((kc + 2) % NSTAGES, (kc + 2) * 32);
        CP_COMMIT();

        const float* Asm = (const float*)(dsm + (kc % NSTAGES) * STAGE_BYTES);
        const float* Bsm = (const float*)((const char*)Asm + ABYTES);

        #pragma unroll
        for (int kk = 0; kk < 4; kk++) {
            const int km = kk * 8 + fc;
            uint32_t afr[2][4];
            #pragma unroll
            for (int mt = 0; mt < 2; mt++) {
                const int mr = warpM * 32 + mt * 16 + fr;
                // m16n8k8 A frag order: a0=(r,c) a1=(r+8,c) a2=(r,c+4) a3=(r+8,c+4)
                afr[mt][0] = __float_as_uint(Asm[mr * APAD + km]);
                afr[mt][1] = __float_as_uint(Asm[(mr + 8) * APAD + km]);
                afr[mt][2] = __float_as_uint(Asm[mr * APAD + km + 4]);
                afr[mt][3] = __float_as_uint(Asm[(mr + 8) * APAD + km + 4]);
            }
            uint32_t bfr[8][2];
            #pragma unroll
            for (int nt = 0; nt < 8; nt++) {
                const int nc = warpN * 64 + nt * 8 + fr;
                bfr[nt][0] = __float_as_uint(Bsm[km * BPAD + nc]);
                bfr[nt][1] = __float_as_uint(Bsm[(km + 4) * BPAD + nc]);
            }
            #pragma unroll
            for (int mt = 0; mt < 2; mt++)
                #pragma unroll
                for (int nt = 0; nt < 8; nt++)
                    mma_tf32(acc[mt][nt], afr[mt], bfr[nt]);
        }
        __syncthreads();
    }

    // ---------------- epilogue ----------------
    #pragma unroll
    for (int mt = 0; mt < 2; mt++) {
        #pragma unroll
        for (int half = 0; half < 2; half++) {
            const int m = m0 + warpM * 32 + mt * 16 + fr + half * 8;
            #pragma unroll
            for (int nt = 0; nt < 8; nt++) {
                const int n = n0 + warpN * 64 + nt * 8 + 2 * fc;
                float2 v = make_float2(acc[mt][nt][half * 2], acc[mt][nt][half * 2 + 1]);
                if (EPI == 0) {
                    const int b = m >> 11, t = m & 2047;
                    const int which = n >> 10, h = (n >> 6) & 15, d = n & 63;
                    *(float2*)&Cout[((((size_t)which * B_ + b) * H_ + h) * T_ + t) * HS + d] = v;
                } else {
                    const float2 bb = *(const float2*)&bias[n];
                    v.x += bb.x; v.y += bb.y;
                    if (EPI == 1) {
                        float2 rr = *(const float2*)&res[(size_t)m * N + n];
                        v.x += rr.x; v.y += rr.y;
                    } else {
                        v.x = tf32r(fmaxf(v.x, 0.f));
                        v.y = tf32r(fmaxf(v.y, 0.f));
                    }
                    *(float2*)&Cout[(size_t)m * N + n] = v;
                }
            }
        }
    }
}

// ======================= causal flash attention ============================
__global__ __launch_bounds__(128)
void attn_kernel(const float* __restrict__ Q,
                 const float* __restrict__ Kt,
                 const float* __restrict__ Vt,
                 float* __restrict__ out) {
    const int bh  = blockIdx.y;
    const int q0  = blockIdx.x * 128;
    const int tid = threadIdx.x;
    const int iq  = q0 + tid;

    __shared__ __align__(16) float Ks[64][HS];
    __shared__ __align__(16) float Vs[64][HS];

    const float4* qp = (const float4*)(Q + ((size_t)bh * T_ + iq) * HS);
    float4 qv[16], ov[16];
    #pragma unroll
    for (int d = 0; d < 16; d++) {
        float4 t = qp[d];
        qv[d] = make_float4(t.x * 0.125f, t.y * 0.125f, t.z * 0.125f, t.w * 0.125f);
        ov[d] = make_float4(0.f, 0.f, 0.f, 0.f);
    }
    float m = -1e30f, l = 0.f;

    const int kend = q0 + 128;
    for (int k0 = 0; k0 < kend; k0 += 64) {
        const float4* kp = (const float4*)(Kt + ((size_t)bh * T_ + k0) * HS);
        const float4* vp = (const float4*)(Vt + ((size_t)bh * T_ + k0) * HS);
        __syncthreads();
        #pragma unroll
        for (int rr = 0; rr < 8; rr++) {
            int idx = rr * 128 + tid;
            ((float4*)Ks)[idx] = kp[idx];
            ((float4*)Vs)[idx] = vp[idx];
        }
        __syncthreads();
        #pragma unroll
        for (int s = 0; s < 4; s++) {
            float p[16];
            float mx = m;
            #pragma unroll
            for (int j = 0; j < 16; j++) {
                const int kj = s * 16 + j;
                const float4* kr = (const float4*)Ks[kj];
                float a = 0.f;
                #pragma unroll
                for (int dd = 0; dd < 16; dd++) {
                    float4 kv = kr[dd];
                    a += qv[dd].x * kv.x + qv[dd].y * kv.y + qv[dd].z * kv.z + qv[dd].w * kv.w;
                }
                p[j] = (k0 + kj <= iq) ? a : -1e30f;
                mx = fmaxf(mx, p[j]);
            }
            const float corr = __expf(m - mx);
            m = mx;
            l *= corr;
            #pragma unroll
            for (int dd = 0; dd < 16; dd++) {
                ov[dd].x *= corr; ov[dd].y *= corr; ov[dd].z *= corr; ov[dd].w *= corr;
            }
            #pragma unroll
            for (int j = 0; j < 16; j++) {
                const float pe = __expf(p[j] - mx);
                l += pe;
                const float4* vr = (const float4*)Vs[s * 16 + j];
                #pragma unroll
                for (int dd = 0; dd < 16; dd++) {
                    float4 vvv = vr[dd];
                    ov[dd].x += pe * vvv.x; ov[dd].y += pe * vvv.y;
                    ov[dd].z += pe * vvv.z; ov[dd].w += pe * vvv.w;
                }
            }
        }
    }
    const int b = bh / H_, h = bh % H_;
    const float inv = 1.0f / l;
    float4* op = (float4*)(out + ((size_t)(b * T_ + iq)) * C_ + h * HS);
    #pragma unroll
    for (int dd = 0; dd < 16; dd++) {
        op[dd] = make_float4(tf32r(ov[dd].x * inv), tf32r(ov[dd].y * inv),
                             tf32r(ov[dd].z * inv), tf32r(ov[dd].w * inv));
    }
}

// ===========================================================================
extern "C" void kernel_launch(void* const* d_in, const int* in_sizes, int n_in,
                              void* d_out, int out_size) {
    const float* x   = (const float*)d_in[0];
    const float* Wq  = (const float*)d_in[1];
    const float* Wk  = (const float*)d_in[2];
    const float* Wv  = (const float*)d_in[3];
    const float* Wo  = (const float*)d_in[4];
    const float* bo  = (const float*)d_in[5];
    const float* g1  = (const float*)d_in[6];
    const float* be1 = (const float*)d_in[7];
    const float* g2  = (const float*)d_in[8];
    const float* be2 = (const float*)d_in[9];
    const float* W1  = (const float*)d_in[10];
    const float* b1  = (const float*)d_in[11];
    const float* W2  = (const float*)d_in[12];
    const float* b2  = (const float*)d_in[13];
    float* out = (float*)d_out;

    float *xn, *qkv, *att, *x1, *xn2, *h, *wqkv, *wo, *w1, *w2;
    cudaGetSymbolAddress((void**)&xn,   g_xn);
    cudaGetSymbolAddress((void**)&qkv,  g_qkv);
    cudaGetSymbolAddress((void**)&att,  g_att);
    cudaGetSymbolAddress((void**)&x1,   g_x1);
    cudaGetSymbolAddress((void**)&xn2,  g_xn2);
    cudaGetSymbolAddress((void**)&h,    g_h);
    cudaGetSymbolAddress((void**)&wqkv, g_wqkv);
    cudaGetSymbolAddress((void**)&wo,   g_wo);
    cudaGetSymbolAddress((void**)&w1,   g_w1);
    cudaGetSymbolAddress((void**)&w2,   g_w2);

    cudaFuncSetAttribute(mm_kernel<0>, cudaFuncAttributeMaxDynamicSharedMemorySize, MM_SMEM);
    cudaFuncSetAttribute(mm_kernel<1>, cudaFuncAttributeMaxDynamicSharedMemorySize, MM_SMEM);
    cudaFuncSetAttribute(mm_kernel<2>, cudaFuncAttributeMaxDynamicSharedMemorySize, MM_SMEM);

    // weight prep (rounded copies, [K][N] row-major)
    pack_qkv_kernel<<<3 * C_ * C_ / 4 / 256, 256>>>(Wq, Wk, Wv, wqkv);
    round_copy_kernel<<<C_ * C_ / 4 / 256, 256>>>(Wo, wo);
    round_copy_kernel<<<C_ * FF / 4 / 256, 256>>>(W1, w1);
    round_copy_kernel<<<FF * C_ / 4 / 256, 256>>>(W2, w2);

    // 1) ln1 (rounded)
    ln_kernel<<<BT, 256>>>(x, g1, be1, xn);
    // 2) fused QKV GEMM: [8192,1024] @ [1024,3072] -> scatter [3,B,H,T,hs]
    mm_kernel<0><<<dim3(3 * C_ / 128, BT / 128), 256, MM_SMEM>>>(xn, wqkv, nullptr, nullptr, qkv, C_, 3 * C_);
    // 3) attention
    attn_kernel<<<dim3(T_ / 128, B_ * H_), 128>>>(qkv, qkv + (size_t)BT * C_, qkv + 2 * (size_t)BT * C_, att);
    // 4) x1 = x + att @ Wo + bo
    mm_kernel<1><<<dim3(C_ / 128, BT / 128), 256, MM_SMEM>>>(att, wo, bo, x, x1, C_, C_);
    // 5) ln2 (rounded)
    ln_kernel<<<BT, 256>>>(x1, g2, be2, xn2);
    // 6) h = relu(xn2 @ W1 + b1) (rounded)
    mm_kernel<2><<<dim3(FF / 128, BT / 128), 256, MM_SMEM>>>(xn2, w1, b1, nullptr, h, C_, FF);
    // 7) out = x1 + h @ W2 + b2
    mm_kernel<1><<<dim3(C_ / 128, BT / 128), 256, MM_SMEM>>>(h, w2, b2, x1, out, FF, C_);
}

// round 5
// speedup vs baseline: 2.7374x; 1.5813x over previous
#include <cuda_runtime.h>
#include <cuda_bf16.h>
#include <cstdint>
#include <cstddef>

#define B_  4
#define T_  2048
#define C_  1024
#define H_  16
#define HS  64
#define BT  (B_ * T_)        // 8192
#define FF  (4 * C_)         // 4096

// ======================= helpers ===========================================
__device__ __forceinline__ float tf32r(float x) {
    uint32_t u;
    asm("cvt.rna.tf32.f32 %0, %1;" : "=r"(u) : "f"(x));
    return __uint_as_float(u);
}
__device__ __forceinline__ uint32_t smem_u32(const void* p) {
    uint32_t a;
    asm("{ .reg .u64 t; cvta.to.shared.u64 t, %1; cvt.u32.u64 %0, t; }" : "=r"(a) : "l"(p));
    return a;
}
__device__ __forceinline__ void cp16(uint32_t dst, const void* src) {
    asm volatile("cp.async.cg.shared.global [%0], [%1], 16;" :: "r"(dst), "l"(src));
}
#define CP_COMMIT() asm volatile("cp.async.commit_group;" ::: "memory")
#define CP_WAIT1()  asm volatile("cp.async.wait_group 1;" ::: "memory")
#define CP_WAIT0()  asm volatile("cp.async.wait_group 0;" ::: "memory")

__device__ __forceinline__ void mma_tf32(float* d, const uint32_t* a, const uint32_t* b) {
    asm volatile(
        "mma.sync.aligned.m16n8k8.row.col.f32.tf32.tf32.f32 "
        "{%0,%1,%2,%3}, {%4,%5,%6,%7}, {%8,%9}, {%0,%1,%2,%3};"
        : "+f"(d[0]), "+f"(d[1]), "+f"(d[2]), "+f"(d[3])
        : "r"(a[0]), "r"(a[1]), "r"(a[2]), "r"(a[3]), "r"(b[0]), "r"(b[1]));
}

// ======================= scratch ===========================================
__device__ float g_xn  [BT * C_];
__device__ float g_qkv [3 * BT * C_];      // [3][B][H][T][hs], tf32-rounded
__device__ float g_att [BT * C_];          // attention out [B,T,C], rounded
__device__ float g_x1  [BT * C_];
__device__ float g_xn2 [BT * C_];
__device__ float g_h   [BT * FF];
__device__ float g_wqkv[C_ * 3 * C_];
__device__ float g_wo  [C_ * C_];
__device__ float g_w1  [C_ * FF];
__device__ float g_w2  [FF * C_];

// ======================= weight prep =======================================
__global__ void pack_qkv_kernel(const float* __restrict__ Wq,
                                const float* __restrict__ Wk,
                                const float* __restrict__ Wv,
                                float* __restrict__ out) {
    int idx = blockIdx.x * blockDim.x + threadIdx.x;
    int n4row = 3 * C_ / 4;
    int k = idx / n4row;
    int n = (idx - k * n4row) * 4;
    int which = n >> 10, h = (n >> 6) & 15, d = n & 63;
    const float* W = (which == 0) ? Wq : (which == 1) ? Wk : Wv;
    float4 v = *(const float4*)&W[((size_t)h * C_ + k) * HS + d];
    v.x = tf32r(v.x); v.y = tf32r(v.y); v.z = tf32r(v.z); v.w = tf32r(v.w);
    *(float4*)&out[(size_t)k * (3 * C_) + n] = v;
}

__global__ void round_copy_kernel(const float* __restrict__ in, float* __restrict__ out) {
    int idx = blockIdx.x * blockDim.x + threadIdx.x;
    float4 v = ((const float4*)in)[idx];
    v.x = tf32r(v.x); v.y = tf32r(v.y); v.z = tf32r(v.z); v.w = tf32r(v.w);
    ((float4*)out)[idx] = v;
}

// ======================= LayerNorm =========================================
__global__ void ln_kernel(const float* __restrict__ x,
                          const float* __restrict__ g,
                          const float* __restrict__ b,
                          float* __restrict__ out) {
    int row = blockIdx.x;
    int tid = threadIdx.x;
    const float4* xr = (const float4*)(x + (size_t)row * C_);
    float4 xv = xr[tid];
    float s  = xv.x + xv.y + xv.z + xv.w;
    float ss = xv.x * xv.x + xv.y * xv.y + xv.z * xv.z + xv.w * xv.w;
    #pragma unroll
    for (int o = 16; o > 0; o >>= 1) {
        s  += __shfl_xor_sync(0xffffffffu, s,  o);
        ss += __shfl_xor_sync(0xffffffffu, ss, o);
    }
    __shared__ float sb[8], sb2[8];
    int wid = tid >> 5, lid = tid & 31;
    if (lid == 0) { sb[wid] = s; sb2[wid] = ss; }
    __syncthreads();
    float tot = 0.f, tot2 = 0.f;
    #pragma unroll
    for (int i = 0; i < 8; i++) { tot += sb[i]; tot2 += sb2[i]; }
    float mean = tot * (1.0f / C_);
    float var  = tot2 * (1.0f / C_) - mean * mean;
    float rstd = rsqrtf(var + 1e-5f);
    float4 gv = ((const float4*)g)[tid];
    float4 bv = ((const float4*)b)[tid];
    float4 ov;
    ov.x = tf32r((xv.x - mean) * rstd * gv.x + bv.x);
    ov.y = tf32r((xv.y - mean) * rstd * gv.y + bv.y);
    ov.z = tf32r((xv.z - mean) * rstd * gv.z + bv.z);
    ov.w = tf32r((xv.w - mean) * rstd * gv.w + bv.w);
    ((float4*)(out + (size_t)row * C_))[tid] = ov;
}

// ======================= TF32 mma.sync GEMM ================================
static constexpr int APAD = 36;
static constexpr int BPAD = 136;
static constexpr int ABYTES = 128 * APAD * 4;
static constexpr int BBYTES = 32 * BPAD * 4;
static constexpr int STAGE_BYTES = ABYTES + BBYTES;
static constexpr int NSTAGES = 3;
static constexpr int MM_SMEM = NSTAGES * STAGE_BYTES;

template<int EPI>
__global__ __launch_bounds__(256)
void mm_kernel(const float* __restrict__ A, const float* __restrict__ Bw,
               const float* __restrict__ bias, const float* __restrict__ res,
               float* __restrict__ Cout, int K, int N) {
    extern __shared__ __align__(16) char dsm[];
    const uint32_t smem0 = smem_u32(dsm);
    const int tid  = threadIdx.x;
    const int wid  = tid >> 5;
    const int lane = tid & 31;
    const int m0 = blockIdx.y * 128;
    const int n0 = blockIdx.x * 128;
    const int nch = K >> 5;

    const int warpM = wid >> 1;
    const int warpN = wid & 1;

    const int arow[4] = { tid >> 3, (tid + 256) >> 3, (tid + 512) >> 3, (tid + 768) >> 3 };
    const int acb  = (tid & 7) << 4;
    const int brow = tid >> 3;
    const int bc0  = (tid & 7) << 4;

    float acc[2][8][4];
    #pragma unroll
    for (int mt = 0; mt < 2; mt++)
        #pragma unroll
        for (int nt = 0; nt < 8; nt++)
            #pragma unroll
            for (int r = 0; r < 4; r++) acc[mt][nt][r] = 0.f;

    auto load_stage = [&](int st, int kpos) {
        uint32_t sa = smem0 + st * STAGE_BYTES;
        uint32_t sbm = sa + ABYTES;
        #pragma unroll
        for (int j = 0; j < 4; j++) {
            int r = arow[j];
            cp16(sa + r * (APAD * 4) + acb,
                 A + (size_t)(m0 + r) * K + kpos + (acb >> 2));
        }
        const float* brp = Bw + (size_t)(kpos + brow) * N + n0;
        #pragma unroll
        for (int j = 0; j < 4; j++) {
            int cb = bc0 + j * 128;
            cp16(sbm + brow * (BPAD * 4) + cb, brp + (cb >> 2));
        }
    };

    load_stage(0, 0); CP_COMMIT();
    load_stage(1, 32); CP_COMMIT();

    const int fr = lane >> 2;
    const int fc = lane & 3;

    for (int kc = 0; kc < nch; kc++) {
        CP_WAIT1();
        __syncthreads();
        if (kc + 2 < nch) load_stage((kc + 2) % NSTAGES, (kc + 2) * 32);
        CP_COMMIT();

        const float* Asm = (const float*)(dsm + (kc % NSTAGES) * STAGE_BYTES);
        const float* Bsm = (const float*)((const char*)Asm + ABYTES);

        #pragma unroll
        for (int kk = 0; kk < 4; kk++) {
            const int km = kk * 8 + fc;
            uint32_t afr[2][4];
            #pragma unroll
            for (int mt = 0; mt < 2; mt++) {
                const int mr = warpM * 32 + mt * 16 + fr;
                afr[mt][0] = __float_as_uint(Asm[mr * APAD + km]);
                afr[mt][1] = __float_as_uint(Asm[(mr + 8) * APAD + km]);
                afr[mt][2] = __float_as_uint(Asm[mr * APAD + km + 4]);
                afr[mt][3] = __float_as_uint(Asm[(mr + 8) * APAD + km + 4]);
            }
            uint32_t bfr[8][2];
            #pragma unroll
            for (int nt = 0; nt < 8; nt++) {
                const int nc = warpN * 64 + nt * 8 + fr;
                bfr[nt][0] = __float_as_uint(Bsm[km * BPAD + nc]);
                bfr[nt][1] = __float_as_uint(Bsm[(km + 4) * BPAD + nc]);
            }
            #pragma unroll
            for (int mt = 0; mt < 2; mt++)
                #pragma unroll
                for (int nt = 0; nt < 8; nt++)
                    mma_tf32(acc[mt][nt], afr[mt], bfr[nt]);
        }
        __syncthreads();
    }

    #pragma unroll
    for (int mt = 0; mt < 2; mt++) {
        #pragma unroll
        for (int half = 0; half < 2; half++) {
            const int m = m0 + warpM * 32 + mt * 16 + fr + half * 8;
            #pragma unroll
            for (int nt = 0; nt < 8; nt++) {
                const int n = n0 + warpN * 64 + nt * 8 + 2 * fc;
                float2 v = make_float2(acc[mt][nt][half * 2], acc[mt][nt][half * 2 + 1]);
                if (EPI == 0) {
                    // q/k/v outputs feed tf32 mma in attention: round now
                    v.x = tf32r(v.x); v.y = tf32r(v.y);
                    const int b = m >> 11, t = m & 2047;
                    const int which = n >> 10, h = (n >> 6) & 15, d = n & 63;
                    *(float2*)&Cout[((((size_t)which * B_ + b) * H_ + h) * T_ + t) * HS + d] = v;
                } else {
                    const float2 bb = *(const float2*)&bias[n];
                    v.x += bb.x; v.y += bb.y;
                    if (EPI == 1) {
                        float2 rr = *(const float2*)&res[(size_t)m * N + n];
                        v.x += rr.x; v.y += rr.y;
                    } else {
                        v.x = tf32r(fmaxf(v.x, 0.f));
                        v.y = tf32r(fmaxf(v.y, 0.f));
                    }
                    *(float2*)&Cout[(size_t)m * N + n] = v;
                }
            }
        }
    }
}

// ======================= tensor-core causal flash attention ================
// CTA: 128 queries (8 warps x 16 rows), K/V tiles of 64 keys, double-buffered.
// smem pitches: K rows 68 floats, V rows 72, P rows 68 (conflict-free frags).
static constexpr int KP = 68;
static constexpr int VP = 72;
static constexpr int PP = 68;
static constexpr int KS_FL = 64 * KP;          // per stage
static constexpr int VS_FL = 64 * VP;
static constexpr int AT_SMEM = (2 * KS_FL + 2 * VS_FL + 128 * PP) * 4;  // 106496 B

__global__ __launch_bounds__(256, 1)
void attn_kernel(const float* __restrict__ Q,
                 const float* __restrict__ K,
                 const float* __restrict__ V,
                 float* __restrict__ out) {
    const int bh = blockIdx.y;
    const int q0 = ((int)gridDim.x - 1 - (int)blockIdx.x) * 128;
    const int tid = threadIdx.x, w = tid >> 5, lane = tid & 31;
    const int qw = q0 + w * 16;
    const int r = lane >> 2, c = lane & 3;

    extern __shared__ __align__(16) float sm[];
    float* Ksm = sm;                    // [2][64][KP]
    float* Vsm = sm + 2 * KS_FL;        // [2][64][VP]
    float* Ps  = sm + 2 * KS_FL + 2 * VS_FL;   // [128][PP]

    const float* Kbh = K + (size_t)bh * T_ * HS;
    const float* Vbh = V + (size_t)bh * T_ * HS;

    // ---- stage Q tile through Ps, pull A-fragments into registers ----
    {
        const float4* qp = (const float4*)(Q + ((size_t)bh * T_ + q0) * HS);
        for (int i = tid; i < 128 * 16; i += 256) {
            int row = i >> 4, c4 = i & 15;
            *(float4*)&Ps[row * PP + c4 * 4] = qp[i];
        }
    }
    __syncthreads();
    float a_q[8][4];
    #pragma unroll
    for (int kc = 0; kc < 8; kc++) {
        const float* base = &Ps[(w * 16 + r) * PP + kc * 8 + c];
        a_q[kc][0] = base[0] * 0.125f;
        a_q[kc][1] = base[8 * PP] * 0.125f;
        a_q[kc][2] = base[4] * 0.125f;
        a_q[kc][3] = base[8 * PP + 4] * 0.125f;
    }

    auto load_kv = [&](int tile, int st) {
        const float4* kp = (const float4*)(Kbh + (size_t)(tile * 64) * HS);
        const float4* vp = (const float4*)(Vbh + (size_t)(tile * 64) * HS);
        float* kd = Ksm + st * KS_FL;
        float* vd = Vsm + st * VS_FL;
        for (int i = tid; i < 64 * 16; i += 256) {
            int row = i >> 4, c4 = i & 15;
            cp16(smem_u32(&kd[row * KP + c4 * 4]), &kp[i]);
            cp16(smem_u32(&vd[row * VP + c4 * 4]), &vp[i]);
        }
    };

    const int ntiles = (q0 + 128) >> 6;
    load_kv(0, 0); CP_COMMIT();

    float o[8][4];
    #pragma unroll
    for (int nt = 0; nt < 8; nt++)
        #pragma unroll
        for (int j = 0; j < 4; j++) o[nt][j] = 0.f;
    float m0 = -1e30f, m1 = -1e30f, l0 = 0.f, l1 = 0.f;

    for (int t = 0; t < ntiles; t++) {
        __syncthreads();                     // prior compute done on other stage
        if (t + 1 < ntiles) { load_kv(t + 1, (t + 1) & 1); CP_COMMIT(); CP_WAIT1(); }
        else CP_WAIT0();
        __syncthreads();                     // stage t data visible

        const int k0 = t * 64;
        if (k0 > qw + 15) continue;          // tile fully masked for this warp
        const float* Kst = Ksm + (t & 1) * KS_FL;
        const float* Vst = Vsm + (t & 1) * VS_FL;

        // ---- S = Q @ K^T ----
        float s[8][4];
        #pragma unroll
        for (int nt = 0; nt < 8; nt++)
            #pragma unroll
            for (int j = 0; j < 4; j++) s[nt][j] = 0.f;
        #pragma unroll
        for (int kc = 0; kc < 8; kc++) {
            const uint32_t* aq = (const uint32_t*)a_q[kc];
            #pragma unroll
            for (int nt = 0; nt < 8; nt++) {
                uint32_t bfr[2];
                bfr[0] = __float_as_uint(Kst[(nt * 8 + r) * KP + kc * 8 + c]);
                bfr[1] = __float_as_uint(Kst[(nt * 8 + r) * KP + kc * 8 + c + 4]);
                mma_tf32(s[nt], aq, bfr);
            }
        }

        // ---- causal mask ----
        if (k0 + 63 > qw) {
            const int row0 = qw + r, row1 = qw + r + 8;
            #pragma unroll
            for (int nt = 0; nt < 8; nt++) {
                const int key = k0 + nt * 8 + 2 * c;
                if (key     > row0) s[nt][0] = -1e30f;
                if (key + 1 > row0) s[nt][1] = -1e30f;
                if (key     > row1) s[nt][2] = -1e30f;
                if (key + 1 > row1) s[nt][3] = -1e30f;
            }
        }

        // ---- online softmax ----
        float mx0 = m0, mx1 = m1;
        #pragma unroll
        for (int nt = 0; nt < 8; nt++) {
            mx0 = fmaxf(mx0, fmaxf(s[nt][0], s[nt][1]));
            mx1 = fmaxf(mx1, fmaxf(s[nt][2], s[nt][3]));
        }
        mx0 = fmaxf(mx0, __shfl_xor_sync(0xffffffffu, mx0, 1));
        mx0 = fmaxf(mx0, __shfl_xor_sync(0xffffffffu, mx0, 2));
        mx1 = fmaxf(mx1, __shfl_xor_sync(0xffffffffu, mx1, 1));
        mx1 = fmaxf(mx1, __shfl_xor_sync(0xffffffffu, mx1, 2));
        const float corr0 = __expf(m0 - mx0);
        const float corr1 = __expf(m1 - mx1);
        m0 = mx0; m1 = mx1;

        __syncwarp();
        float ls0 = 0.f, ls1 = 0.f;
        float* prow0 = &Ps[(w * 16 + r) * PP];
        float* prow1 = &Ps[(w * 16 + r + 8) * PP];
        #pragma unroll
        for (int nt = 0; nt < 8; nt++) {
            float p0 = tf32r(__expf(s[nt][0] - mx0));
            float p1 = tf32r(__expf(s[nt][1] - mx0));
            float p2 = tf32r(__expf(s[nt][2] - mx1));
            float p3 = tf32r(__expf(s[nt][3] - mx1));
            ls0 += p0 + p1; ls1 += p2 + p3;
            *(float2*)&prow0[nt * 8 + 2 * c] = make_float2(p0, p1);
            *(float2*)&prow1[nt * 8 + 2 * c] = make_float2(p2, p3);
        }
        ls0 += __shfl_xor_sync(0xffffffffu, ls0, 1);
        ls0 += __shfl_xor_sync(0xffffffffu, ls0, 2);
        ls1 += __shfl_xor_sync(0xffffffffu, ls1, 1);
        ls1 += __shfl_xor_sync(0xffffffffu, ls1, 2);
        l0 = l0 * corr0 + ls0;
        l1 = l1 * corr1 + ls1;

        #pragma unroll
        for (int nt = 0; nt < 8; nt++) {
            o[nt][0] *= corr0; o[nt][1] *= corr0;
            o[nt][2] *= corr1; o[nt][3] *= corr1;
        }
        __syncwarp();

        // ---- O += P @ V ----
        #pragma unroll
        for (int kc = 0; kc < 8; kc++) {
            uint32_t afr[4];
            afr[0] = __float_as_uint(Ps[(w * 16 + r) * PP + kc * 8 + c]);
            afr[1] = __float_as_uint(Ps[(w * 16 + r + 8) * PP + kc * 8 + c]);
            afr[2] = __float_as_uint(Ps[(w * 16 + r) * PP + kc * 8 + c + 4]);
            afr[3] = __float_as_uint(Ps[(w * 16 + r + 8) * PP + kc * 8 + c + 4]);
            #pragma unroll
            for (int nt = 0; nt < 8; nt++) {
                uint32_t bfr[2];
                bfr[0] = __float_as_uint(Vst[(kc * 8 + c) * VP + nt * 8 + r]);
                bfr[1] = __float_as_uint(Vst[(kc * 8 + c + 4) * VP + nt * 8 + r]);
                mma_tf32(o[nt], afr, bfr);
            }
        }
    }

    // ---- write out (tf32-rounded, feeds Wo GEMM) ----
    const float inv0 = 1.0f / l0, inv1 = 1.0f / l1;
    const int b = bh >> 4, h = bh & 15;
    float* ob0 = out + ((size_t)(b * T_ + qw + r)) * C_ + h * HS;
    float* ob1 = out + ((size_t)(b * T_ + qw + r + 8)) * C_ + h * HS;
    #pragma unroll
    for (int nt = 0; nt < 8; nt++) {
        *(float2*)&ob0[nt * 8 + 2 * c] =
            make_float2(tf32r(o[nt][0] * inv0), tf32r(o[nt][1] * inv0));
        *(float2*)&ob1[nt * 8 + 2 * c] =
            make_float2(tf32r(o[nt][2] * inv1), tf32r(o[nt][3] * inv1));
    }
}

// ===========================================================================
extern "C" void kernel_launch(void* const* d_in, const int* in_sizes, int n_in,
                              void* d_out, int out_size) {
    const float* x   = (const float*)d_in[0];
    const float* Wq  = (const float*)d_in[1];
    const float* Wk  = (const float*)d_in[2];
    const float* Wv  = (const float*)d_in[3];
    const float* Wo  = (const float*)d_in[4];
    const float* bo  = (const float*)d_in[5];
    const float* g1  = (const float*)d_in[6];
    const float* be1 = (const float*)d_in[7];
    const float* g2  = (const float*)d_in[8];
    const float* be2 = (const float*)d_in[9];
    const float* W1  = (const float*)d_in[10];
    const float* b1  = (const float*)d_in[11];
    const float* W2  = (const float*)d_in[12];
    const float* b2  = (const float*)d_in[13];
    float* out = (float*)d_out;

    float *xn, *qkv, *att, *x1, *xn2, *h, *wqkv, *wo, *w1, *w2;
    cudaGetSymbolAddress((void**)&xn,   g_xn);
    cudaGetSymbolAddress((void**)&qkv,  g_qkv);
    cudaGetSymbolAddress((void**)&att,  g_att);
    cudaGetSymbolAddress((void**)&x1,   g_x1);
    cudaGetSymbolAddress((void**)&xn2,  g_xn2);
    cudaGetSymbolAddress((void**)&h,    g_h);
    cudaGetSymbolAddress((void**)&wqkv, g_wqkv);
    cudaGetSymbolAddress((void**)&wo,   g_wo);
    cudaGetSymbolAddress((void**)&w1,   g_w1);
    cudaGetSymbolAddress((void**)&w2,   g_w2);

    cudaFuncSetAttribute(mm_kernel<0>, cudaFuncAttributeMaxDynamicSharedMemorySize, MM_SMEM);
    cudaFuncSetAttribute(mm_kernel<1>, cudaFuncAttributeMaxDynamicSharedMemorySize, MM_SMEM);
    cudaFuncSetAttribute(mm_kernel<2>, cudaFuncAttributeMaxDynamicSharedMemorySize, MM_SMEM);
    cudaFuncSetAttribute(attn_kernel,  cudaFuncAttributeMaxDynamicSharedMemorySize, AT_SMEM);

    pack_qkv_kernel<<<3 * C_ * C_ / 4 / 256, 256>>>(Wq, Wk, Wv, wqkv);
    round_copy_kernel<<<C_ * C_ / 4 / 256, 256>>>(Wo, wo);
    round_copy_kernel<<<C_ * FF / 4 / 256, 256>>>(W1, w1);
    round_copy_kernel<<<FF * C_ / 4 / 256, 256>>>(W2, w2);

    // 1) ln1
    ln_kernel<<<BT, 256>>>(x, g1, be1, xn);
    // 2) fused QKV GEMM -> scatter [3,B,H,T,hs] (tf32-rounded)
    mm_kernel<0><<<dim3(3 * C_ / 128, BT / 128), 256, MM_SMEM>>>(xn, wqkv, nullptr, nullptr, qkv, C_, 3 * C_);
    // 3) tensor-core flash attention
    attn_kernel<<<dim3(T_ / 128, B_ * H_), 256, AT_SMEM>>>(
        qkv, qkv + (size_t)BT * C_, qkv + 2 * (size_t)BT * C_, att);
    // 4) x1 = x + att @ Wo + bo
    mm_kernel<1><<<dim3(C_ / 128, BT / 128), 256, MM_SMEM>>>(att, wo, bo, x, x1, C_, C_);
    // 5) ln2
    ln_kernel<<<BT, 256>>>(x1, g2, be2, xn2);
    // 6) h = relu(xn2 @ W1 + b1)
    mm_kernel<2><<<dim3(FF / 128, BT / 128), 256, MM_SMEM>>>(xn2, w1, b1, nullptr, h, C_, FF);
    // 7) out = x1 + h @ W2 + b2
    mm_kernel<1><<<dim3(C_ / 128, BT / 128), 256, MM_SMEM>>>(h, w2, b2, x1, out, FF, C_);
}

// round 6
// speedup vs baseline: 4.4302x; 1.6184x over previous
#include <cuda_runtime.h>
#include <cuda_bf16.h>
#include <cstdint>
#include <cstddef>

#define B_  4
#define T_  2048
#define C_  1024
#define H_  16
#define HS  64
#define BT  (B_ * T_)        // 8192
#define FF  (4 * C_)         // 4096

// ======================= helpers ===========================================
__device__ __forceinline__ float tf32r(float x) {
    uint32_t u;
    asm("cvt.rna.tf32.f32 %0, %1;" : "=r"(u) : "f"(x));
    return __uint_as_float(u);
}
__device__ __forceinline__ uint32_t smem_u32(const void* p) {
    uint32_t a;
    asm("{ .reg .u64 t; cvta.to.shared.u64 t, %1; cvt.u32.u64 %0, t; }" : "=r"(a) : "l"(p));
    return a;
}
__device__ __forceinline__ void cp16(uint32_t dst, const void* src) {
    asm volatile("cp.async.cg.shared.global [%0], [%1], 16;" :: "r"(dst), "l"(src));
}
#define CP_COMMIT() asm volatile("cp.async.commit_group;" ::: "memory")
#define CP_WAIT1()  asm volatile("cp.async.wait_group 1;" ::: "memory")
#define CP_WAIT0()  asm volatile("cp.async.wait_group 0;" ::: "memory")

__device__ __forceinline__ void mma_tf32(float* d, const uint32_t* a, const uint32_t* b) {
    asm volatile(
        "mma.sync.aligned.m16n8k8.row.col.f32.tf32.tf32.f32 "
        "{%0,%1,%2,%3}, {%4,%5,%6,%7}, {%8,%9}, {%0,%1,%2,%3};"
        : "+f"(d[0]), "+f"(d[1]), "+f"(d[2]), "+f"(d[3])
        : "r"(a[0]), "r"(a[1]), "r"(a[2]), "r"(a[3]), "r"(b[0]), "r"(b[1]));
}

// ======================= scratch ===========================================
__device__ float g_xn  [BT * C_];
__device__ float g_qkv [3 * BT * C_];      // [3][B][H][T][hs], tf32-rounded
__device__ float g_att [BT * C_];
__device__ float g_x1  [BT * C_];
__device__ float g_xn2 [BT * C_];
__device__ float g_h   [BT * FF];
__device__ float g_wqkv[C_ * 3 * C_];
__device__ float g_wo  [C_ * C_];
__device__ float g_w1  [C_ * FF];
__device__ float g_w2  [FF * C_];

// ======================= weight prep =======================================
__global__ void pack_qkv_kernel(const float* __restrict__ Wq,
                                const float* __restrict__ Wk,
                                const float* __restrict__ Wv,
                                float* __restrict__ out) {
    int idx = blockIdx.x * blockDim.x + threadIdx.x;
    int n4row = 3 * C_ / 4;
    int k = idx / n4row;
    int n = (idx - k * n4row) * 4;
    int which = n >> 10, h = (n >> 6) & 15, d = n & 63;
    const float* W = (which == 0) ? Wq : (which == 1) ? Wk : Wv;
    float4 v = *(const float4*)&W[((size_t)h * C_ + k) * HS + d];
    v.x = tf32r(v.x); v.y = tf32r(v.y); v.z = tf32r(v.z); v.w = tf32r(v.w);
    *(float4*)&out[(size_t)k * (3 * C_) + n] = v;
}

__global__ void round_copy_kernel(const float* __restrict__ in, float* __restrict__ out) {
    int idx = blockIdx.x * blockDim.x + threadIdx.x;
    float4 v = ((const float4*)in)[idx];
    v.x = tf32r(v.x); v.y = tf32r(v.y); v.z = tf32r(v.z); v.w = tf32r(v.w);
    ((float4*)out)[idx] = v;
}

// ======================= LayerNorm =========================================
__global__ void ln_kernel(const float* __restrict__ x,
                          const float* __restrict__ g,
                          const float* __restrict__ b,
                          float* __restrict__ out) {
    int row = blockIdx.x;
    int tid = threadIdx.x;
    const float4* xr = (const float4*)(x + (size_t)row * C_);
    float4 xv = xr[tid];
    float s  = xv.x + xv.y + xv.z + xv.w;
    float ss = xv.x * xv.x + xv.y * xv.y + xv.z * xv.z + xv.w * xv.w;
    #pragma unroll
    for (int o = 16; o > 0; o >>= 1) {
        s  += __shfl_xor_sync(0xffffffffu, s,  o);
        ss += __shfl_xor_sync(0xffffffffu, ss, o);
    }
    __shared__ float sb[8], sb2[8];
    int wid = tid >> 5, lid = tid & 31;
    if (lid == 0) { sb[wid] = s; sb2[wid] = ss; }
    __syncthreads();
    float tot = 0.f, tot2 = 0.f;
    #pragma unroll
    for (int i = 0; i < 8; i++) { tot += sb[i]; tot2 += sb2[i]; }
    float mean = tot * (1.0f / C_);
    float var  = tot2 * (1.0f / C_) - mean * mean;
    float rstd = rsqrtf(var + 1e-5f);
    float4 gv = ((const float4*)g)[tid];
    float4 bv = ((const float4*)b)[tid];
    float4 ov;
    ov.x = tf32r((xv.x - mean) * rstd * gv.x + bv.x);
    ov.y = tf32r((xv.y - mean) * rstd * gv.y + bv.y);
    ov.z = tf32r((xv.z - mean) * rstd * gv.z + bv.z);
    ov.w = tf32r((xv.w - mean) * rstd * gv.w + bv.w);
    ((float4*)(out + (size_t)row * C_))[tid] = ov;
}

// ======================= TF32 mma.sync GEMM ================================
// CTA tile 128x256, BK=32, 8 warps (2M x 4N), warp tile 64x64.
// 3-stage cp.async pipeline, ONE __syncthreads per K-chunk.
static constexpr int BM = 128, BN = 256, BK = 32;
static constexpr int APAD = 36;    // A row pitch in floats
static constexpr int BPAD = 264;   // B row pitch in floats
static constexpr int ABYTES = BM * APAD * 4;          // 18432
static constexpr int BBYTES = BK * BPAD * 4;          // 33792
static constexpr int STAGE_BYTES = ABYTES + BBYTES;   // 52224
static constexpr int NSTAGES = 3;
static constexpr int MM_SMEM = NSTAGES * STAGE_BYTES; // 156672

template<int EPI>
__global__ __launch_bounds__(256, 1)
void mm_kernel(const float* __restrict__ A, const float* __restrict__ Bw,
               const float* __restrict__ bias, const float* __restrict__ res,
               float* __restrict__ Cout, int K, int N) {
    extern __shared__ __align__(16) char dsm[];
    const uint32_t smem0 = smem_u32(dsm);
    const int tid  = threadIdx.x;
    const int wid  = tid >> 5;
    const int lane = tid & 31;
    const int m0 = blockIdx.y * BM;
    const int n0 = blockIdx.x * BN;
    const int nch = K >> 5;

    const int warpM = wid >> 2;           // 0..1 (64 rows each)
    const int warpN = wid & 3;            // 0..3 (64 cols each)

    // loader indices
    const int arow0 = tid >> 3;           // + {0,32,64,96}
    const int acb   = (tid & 7) << 4;     // 16B chunk within 128B row
    const int brow  = tid >> 3;           // 0..31
    const int bc0   = (tid & 7) << 4;     // + j*128 (8 chunks/row)

    float acc[4][8][4];
    #pragma unroll
    for (int mt = 0; mt < 4; mt++)
        #pragma unroll
        for (int nt = 0; nt < 8; nt++)
            #pragma unroll
            for (int r = 0; r < 4; r++) acc[mt][nt][r] = 0.f;

    auto load_stage = [&](int st, int kpos) {
        uint32_t sa  = smem0 + st * STAGE_BYTES;
        uint32_t sbm = sa + ABYTES;
        #pragma unroll
        for (int j = 0; j < 4; j++) {
            int r = arow0 + j * 32;
            cp16(sa + r * (APAD * 4) + acb,
                 A + (size_t)(m0 + r) * K + kpos + (acb >> 2));
        }
        const float* brp = Bw + (size_t)(kpos + brow) * N + n0;
        #pragma unroll
        for (int j = 0; j < 8; j++) {
            int cb = bc0 + j * 128;           // 0..1023 bytes
            cp16(sbm + brow * (BPAD * 4) + cb, brp + (cb >> 2));
        }
    };

    load_stage(0, 0); CP_COMMIT();
    load_stage(1, 32); CP_COMMIT();

    const int fr = lane >> 2;      // 0..7
    const int fc = lane & 3;       // 0..3

    for (int kc = 0; kc < nch; kc++) {
        CP_WAIT1();
        __syncthreads();    // stage kc ready; stage kc+2 (==kc-1 mod 3) drained
        if (kc + 2 < nch) load_stage((kc + 2) % NSTAGES, (kc + 2) * 32);
        CP_COMMIT();

        const float* Asm = (const float*)(dsm + (kc % NSTAGES) * STAGE_BYTES);
        const float* Bsm = (const float*)((const char*)Asm + ABYTES);

        #pragma unroll
        for (int kk = 0; kk < 4; kk++) {
            const int km = kk * 8 + fc;
            uint32_t afr[4][4];
            #pragma unroll
            for (int mt = 0; mt < 4; mt++) {
                const int mr = warpM * 64 + mt * 16 + fr;
                afr[mt][0] = __float_as_uint(Asm[mr * APAD + km]);
                afr[mt][1] = __float_as_uint(Asm[(mr + 8) * APAD + km]);
                afr[mt][2] = __float_as_uint(Asm[mr * APAD + km + 4]);
                afr[mt][3] = __float_as_uint(Asm[(mr + 8) * APAD + km + 4]);
            }
            uint32_t bfr[8][2];
            #pragma unroll
            for (int nt = 0; nt < 8; nt++) {
                const int nc = warpN * 64 + nt * 8 + fr;
                bfr[nt][0] = __float_as_uint(Bsm[km * BPAD + nc]);
                bfr[nt][1] = __float_as_uint(Bsm[(km + 4) * BPAD + nc]);
            }
            #pragma unroll
            for (int mt = 0; mt < 4; mt++)
                #pragma unroll
                for (int nt = 0; nt < 8; nt++)
                    mma_tf32(acc[mt][nt], afr[mt], bfr[nt]);
        }
    }

    // ---------------- epilogue ----------------
    #pragma unroll
    for (int mt = 0; mt < 4; mt++) {
        #pragma unroll
        for (int half = 0; half < 2; half++) {
            const int m = m0 + warpM * 64 + mt * 16 + fr + half * 8;
            #pragma unroll
            for (int nt = 0; nt < 8; nt++) {
                const int n = n0 + warpN * 64 + nt * 8 + 2 * fc;
                float2 v = make_float2(acc[mt][nt][half * 2], acc[mt][nt][half * 2 + 1]);
                if (EPI == 0) {
                    v.x = tf32r(v.x); v.y = tf32r(v.y);
                    const int b = m >> 11, t = m & 2047;
                    const int which = n >> 10, h = (n >> 6) & 15, d = n & 63;
                    *(float2*)&Cout[((((size_t)which * B_ + b) * H_ + h) * T_ + t) * HS + d] = v;
                } else {
                    const float2 bb = *(const float2*)&bias[n];
                    v.x += bb.x; v.y += bb.y;
                    if (EPI == 1) {
                        float2 rr = *(const float2*)&res[(size_t)m * N + n];
                        v.x += rr.x; v.y += rr.y;
                    } else {
                        v.x = tf32r(fmaxf(v.x, 0.f));
                        v.y = tf32r(fmaxf(v.y, 0.f));
                    }
                    *(float2*)&Cout[(size_t)m * N + n] = v;
                }
            }
        }
    }
}

// ======================= tensor-core causal flash attention ================
static constexpr int KP = 68;
static constexpr int VP = 72;
static constexpr int PP = 68;
static constexpr int KS_FL = 64 * KP;
static constexpr int VS_FL = 64 * VP;
static constexpr int AT_SMEM = (2 * KS_FL + 2 * VS_FL + 128 * PP) * 4;

__global__ __launch_bounds__(256, 1)
void attn_kernel(const float* __restrict__ Q,
                 const float* __restrict__ K,
                 const float* __restrict__ V,
                 float* __restrict__ out) {
    const int bh = blockIdx.y;
    const int q0 = ((int)gridDim.x - 1 - (int)blockIdx.x) * 128;
    const int tid = threadIdx.x, w = tid >> 5, lane = tid & 31;
    const int qw = q0 + w * 16;
    const int r = lane >> 2, c = lane & 3;

    extern __shared__ __align__(16) float sm[];
    float* Ksm = sm;
    float* Vsm = sm + 2 * KS_FL;
    float* Ps  = sm + 2 * KS_FL + 2 * VS_FL;

    const float* Kbh = K + (size_t)bh * T_ * HS;
    const float* Vbh = V + (size_t)bh * T_ * HS;

    {
        const float4* qp = (const float4*)(Q + ((size_t)bh * T_ + q0) * HS);
        for (int i = tid; i < 128 * 16; i += 256) {
            int row = i >> 4, c4 = i & 15;
            *(float4*)&Ps[row * PP + c4 * 4] = qp[i];
        }
    }
    __syncthreads();
    float a_q[8][4];
    #pragma unroll
    for (int kc = 0; kc < 8; kc++) {
        const float* base = &Ps[(w * 16 + r) * PP + kc * 8 + c];
        a_q[kc][0] = base[0] * 0.125f;
        a_q[kc][1] = base[8 * PP] * 0.125f;
        a_q[kc][2] = base[4] * 0.125f;
        a_q[kc][3] = base[8 * PP + 4] * 0.125f;
    }

    auto load_kv = [&](int tile, int st) {
        const float4* kp = (const float4*)(Kbh + (size_t)(tile * 64) * HS);
        const float4* vp = (const float4*)(Vbh + (size_t)(tile * 64) * HS);
        float* kd = Ksm + st * KS_FL;
        float* vd = Vsm + st * VS_FL;
        for (int i = tid; i < 64 * 16; i += 256) {
            int row = i >> 4, c4 = i & 15;
            cp16(smem_u32(&kd[row * KP + c4 * 4]), &kp[i]);
            cp16(smem_u32(&vd[row * VP + c4 * 4]), &vp[i]);
        }
    };

    const int ntiles = (q0 + 128) >> 6;
    load_kv(0, 0); CP_COMMIT();

    float o[8][4];
    #pragma unroll
    for (int nt = 0; nt < 8; nt++)
        #pragma unroll
        for (int j = 0; j < 4; j++) o[nt][j] = 0.f;
    float m0 = -1e30f, m1 = -1e30f, l0 = 0.f, l1 = 0.f;

    for (int t = 0; t < ntiles; t++) {
        __syncthreads();
        if (t + 1 < ntiles) { load_kv(t + 1, (t + 1) & 1); CP_COMMIT(); CP_WAIT1(); }
        else CP_WAIT0();
        __syncthreads();

        const int k0 = t * 64;
        if (k0 > qw + 15) continue;
        const float* Kst = Ksm + (t & 1) * KS_FL;
        const float* Vst = Vsm + (t & 1) * VS_FL;

        float s[8][4];
        #pragma unroll
        for (int nt = 0; nt < 8; nt++)
            #pragma unroll
            for (int j = 0; j < 4; j++) s[nt][j] = 0.f;
        #pragma unroll
        for (int kc = 0; kc < 8; kc++) {
            const uint32_t* aq = (const uint32_t*)a_q[kc];
            #pragma unroll
            for (int nt = 0; nt < 8; nt++) {
                uint32_t bfr[2];
                bfr[0] = __float_as_uint(Kst[(nt * 8 + r) * KP + kc * 8 + c]);
                bfr[1] = __float_as_uint(Kst[(nt * 8 + r) * KP + kc * 8 + c + 4]);
                mma_tf32(s[nt], aq, bfr);
            }
        }

        if (k0 + 63 > qw) {
            const int row0 = qw + r, row1 = qw + r + 8;
            #pragma unroll
            for (int nt = 0; nt < 8; nt++) {
                const int key = k0 + nt * 8 + 2 * c;
                if (key     > row0) s[nt][0] = -1e30f;
                if (key + 1 > row0) s[nt][1] = -1e30f;
                if (key     > row1) s[nt][2] = -1e30f;
                if (key + 1 > row1) s[nt][3] = -1e30f;
            }
        }

        float mx0 = m0, mx1 = m1;
        #pragma unroll
        for (int nt = 0; nt < 8; nt++) {
            mx0 = fmaxf(mx0, fmaxf(s[nt][0], s[nt][1]));
            mx1 = fmaxf(mx1, fmaxf(s[nt][2], s[nt][3]));
        }
        mx0 = fmaxf(mx0, __shfl_xor_sync(0xffffffffu, mx0, 1));
        mx0 = fmaxf(mx0, __shfl_xor_sync(0xffffffffu, mx0, 2));
        mx1 = fmaxf(mx1, __shfl_xor_sync(0xffffffffu, mx1, 1));
        mx1 = fmaxf(mx1, __shfl_xor_sync(0xffffffffu, mx1, 2));
        const float corr0 = __expf(m0 - mx0);
        const float corr1 = __expf(m1 - mx1);
        m0 = mx0; m1 = mx1;

        __syncwarp();
        float ls0 = 0.f, ls1 = 0.f;
        float* prow0 = &Ps[(w * 16 + r) * PP];
        float* prow1 = &Ps[(w * 16 + r + 8) * PP];
        #pragma unroll
        for (int nt = 0; nt < 8; nt++) {
            float p0 = tf32r(__expf(s[nt][0] - mx0));
            float p1 = tf32r(__expf(s[nt][1] - mx0));
            float p2 = tf32r(__expf(s[nt][2] - mx1));
            float p3 = tf32r(__expf(s[nt][3] - mx1));
            ls0 += p0 + p1; ls1 += p2 + p3;
            *(float2*)&prow0[nt * 8 + 2 * c] = make_float2(p0, p1);
            *(float2*)&prow1[nt * 8 + 2 * c] = make_float2(p2, p3);
        }
        ls0 += __shfl_xor_sync(0xffffffffu, ls0, 1);
        ls0 += __shfl_xor_sync(0xffffffffu, ls0, 2);
        ls1 += __shfl_xor_sync(0xffffffffu, ls1, 1);
        ls1 += __shfl_xor_sync(0xffffffffu, ls1, 2);
        l0 = l0 * corr0 + ls0;
        l1 = l1 * corr1 + ls1;

        #pragma unroll
        for (int nt = 0; nt < 8; nt++) {
            o[nt][0] *= corr0; o[nt][1] *= corr0;
            o[nt][2] *= corr1; o[nt][3] *= corr1;
        }
        __syncwarp();

        #pragma unroll
        for (int kc = 0; kc < 8; kc++) {
            uint32_t afr[4];
            afr[0] = __float_as_uint(Ps[(w * 16 + r) * PP + kc * 8 + c]);
            afr[1] = __float_as_uint(Ps[(w * 16 + r + 8) * PP + kc * 8 + c]);
            afr[2] = __float_as_uint(Ps[(w * 16 + r) * PP + kc * 8 + c + 4]);
            afr[3] = __float_as_uint(Ps[(w * 16 + r + 8) * PP + kc * 8 + c + 4]);
            #pragma unroll
            for (int nt = 0; nt < 8; nt++) {
                uint32_t bfr[2];
                bfr[0] = __float_as_uint(Vst[(kc * 8 + c) * VP + nt * 8 + r]);
                bfr[1] = __float_as_uint(Vst[(kc * 8 + c + 4) * VP + nt * 8 + r]);
                mma_tf32(o[nt], afr, bfr);
            }
        }
    }

    const float inv0 = 1.0f / l0, inv1 = 1.0f / l1;
    const int b = bh >> 4, h = bh & 15;
    float* ob0 = out + ((size_t)(b * T_ + qw + r)) * C_ + h * HS;
    float* ob1 = out + ((size_t)(b * T_ + qw + r + 8)) * C_ + h * HS;
    #pragma unroll
    for (int nt = 0; nt < 8; nt++) {
        *(float2*)&ob0[nt * 8 + 2 * c] =
            make_float2(tf32r(o[nt][0] * inv0), tf32r(o[nt][1] * inv0));
        *(float2*)&ob1[nt * 8 + 2 * c] =
            make_float2(tf32r(o[nt][2] * inv1), tf32r(o[nt][3] * inv1));
    }
}

// ===========================================================================
extern "C" void kernel_launch(void* const* d_in, const int* in_sizes, int n_in,
                              void* d_out, int out_size) {
    const float* x   = (const float*)d_in[0];
    const float* Wq  = (const float*)d_in[1];
    const float* Wk  = (const float*)d_in[2];
    const float* Wv  = (const float*)d_in[3];
    const float* Wo  = (const float*)d_in[4];
    const float* bo  = (const float*)d_in[5];
    const float* g1  = (const float*)d_in[6];
    const float* be1 = (const float*)d_in[7];
    const float* g2  = (const float*)d_in[8];
    const float* be2 = (const float*)d_in[9];
    const float* W1  = (const float*)d_in[10];
    const float* b1  = (const float*)d_in[11];
    const float* W2  = (const float*)d_in[12];
    const float* b2  = (const float*)d_in[13];
    float* out = (float*)d_out;

    float *xn, *qkv, *att, *x1, *xn2, *h, *wqkv, *wo, *w1, *w2;
    cudaGetSymbolAddress((void**)&xn,   g_xn);
    cudaGetSymbolAddress((void**)&qkv,  g_qkv);
    cudaGetSymbolAddress((void**)&att,  g_att);
    cudaGetSymbolAddress((void**)&x1,   g_x1);
    cudaGetSymbolAddress((void**)&xn2,  g_xn2);
    cudaGetSymbolAddress((void**)&h,    g_h);
    cudaGetSymbolAddress((void**)&wqkv, g_wqkv);
    cudaGetSymbolAddress((void**)&wo,   g_wo);
    cudaGetSymbolAddress((void**)&w1,   g_w1);
    cudaGetSymbolAddress((void**)&w2,   g_w2);

    cudaFuncSetAttribute(mm_kernel<0>, cudaFuncAttributeMaxDynamicSharedMemorySize, MM_SMEM);
    cudaFuncSetAttribute(mm_kernel<1>, cudaFuncAttributeMaxDynamicSharedMemorySize, MM_SMEM);
    cudaFuncSetAttribute(mm_kernel<2>, cudaFuncAttributeMaxDynamicSharedMemorySize, MM_SMEM);
    cudaFuncSetAttribute(attn_kernel,  cudaFuncAttributeMaxDynamicSharedMemorySize, AT_SMEM);

    pack_qkv_kernel<<<3 * C_ * C_ / 4 / 256, 256>>>(Wq, Wk, Wv, wqkv);
    round_copy_kernel<<<C_ * C_ / 4 / 256, 256>>>(Wo, wo);
    round_copy_kernel<<<C_ * FF / 4 / 256, 256>>>(W1, w1);
    round_copy_kernel<<<FF * C_ / 4 / 256, 256>>>(W2, w2);

    // 1) ln1
    ln_kernel<<<BT, 256>>>(x, g1, be1, xn);
    // 2) fused QKV GEMM -> scatter [3,B,H,T,hs]
    mm_kernel<0><<<dim3(3 * C_ / BN, BT / BM), 256, MM_SMEM>>>(xn, wqkv, nullptr, nullptr, qkv, C_, 3 * C_);
    // 3) tensor-core flash attention
    attn_kernel<<<dim3(T_ / 128, B_ * H_), 256, AT_SMEM>>>(
        qkv, qkv + (size_t)BT * C_, qkv + 2 * (size_t)BT * C_, att);
    // 4) x1 = x + att @ Wo + bo
    mm_kernel<1><<<dim3(C_ / BN, BT / BM), 256, MM_SMEM>>>(att, wo, bo, x, x1, C_, C_);
    // 5) ln2
    ln_kernel<<<BT, 256>>>(x1, g2, be2, xn2);
    // 6) h = relu(xn2 @ W1 + b1)
    mm_kernel<2><<<dim3(FF / BN, BT / BM), 256, MM_SMEM>>>(xn2, w1, b1, nullptr, h, C_, FF);
    // 7) out = x1 + h @ W2 + b2
    mm_kernel<1><<<dim3(C_ / BN, BT / BM), 256, MM_SMEM>>>(h, w2, b2, x1, out, FF, C_);
}

// round 7
// speedup vs baseline: 4.4565x; 1.0059x over previous
#include <cuda_runtime.h>
#include <cuda_bf16.h>
#include <cstdint>
#include <cstddef>

#define B_  4
#define T_  2048
#define C_  1024
#define H_  16
#define HS  64
#define BT  (B_ * T_)        // 8192
#define FF  (4 * C_)         // 4096

// ======================= helpers ===========================================
__device__ __forceinline__ float tf32r(float x) {
    uint32_t u;
    asm("cvt.rna.tf32.f32 %0, %1;" : "=r"(u) : "f"(x));
    return __uint_as_float(u);
}
__device__ __forceinline__ uint32_t smem_u32(const void* p) {
    uint32_t a;
    asm("{ .reg .u64 t; cvta.to.shared.u64 t, %1; cvt.u32.u64 %0, t; }" : "=r"(a) : "l"(p));
    return a;
}
__device__ __forceinline__ void cp16(uint32_t dst, const void* src) {
    asm volatile("cp.async.cg.shared.global [%0], [%1], 16;" :: "r"(dst), "l"(src));
}
#define CP_COMMIT() asm volatile("cp.async.commit_group;" ::: "memory")
#define CP_WAIT1()  asm volatile("cp.async.wait_group 1;" ::: "memory")
#define CP_WAIT0()  asm volatile("cp.async.wait_group 0;" ::: "memory")

__device__ __forceinline__ void mma_tf32(float* d, const uint32_t* a, const uint32_t* b) {
    asm volatile(
        "mma.sync.aligned.m16n8k8.row.col.f32.tf32.tf32.f32 "
        "{%0,%1,%2,%3}, {%4,%5,%6,%7}, {%8,%9}, {%0,%1,%2,%3};"
        : "+f"(d[0]), "+f"(d[1]), "+f"(d[2]), "+f"(d[3])
        : "r"(a[0]), "r"(a[1]), "r"(a[2]), "r"(a[3]), "r"(b[0]), "r"(b[1]));
}

// ======================= scratch ===========================================
__device__ float g_xn  [BT * C_];
__device__ float g_qkv [3 * BT * C_];      // [3][B][H][T][hs], tf32-rounded
__device__ float g_att [BT * C_];
__device__ float g_x1  [BT * C_];
__device__ float g_xn2 [BT * C_];
__device__ float g_h   [BT * FF];
__device__ float g_wqkv[C_ * 3 * C_];
__device__ float g_wo  [C_ * C_];
__device__ float g_w1  [C_ * FF];
__device__ float g_w2  [FF * C_];

// ======================= fused weight prep =================================
// region 0: pack Wq/Wk/Wv [H,C,hs] -> wqkv [C, 3072]   (786432 float4)
// region 1: wo   (262144 float4)   region 2: w1 (1048576)   region 3: w2 (1048576)
__global__ void prep_kernel(const float* __restrict__ Wq, const float* __restrict__ Wk,
                            const float* __restrict__ Wv, const float* __restrict__ Wo,
                            const float* __restrict__ W1, const float* __restrict__ W2,
                            float* __restrict__ wqkv, float* __restrict__ wo,
                            float* __restrict__ w1, float* __restrict__ w2) {
    int idx = blockIdx.x * blockDim.x + threadIdx.x;
    const int NQ = 3 * C_ * C_ / 4;          // 786432
    const int NO = C_ * C_ / 4;              // 262144
    const int N1 = C_ * FF / 4;              // 1048576
    if (idx < NQ) {
        int n4row = 3 * C_ / 4;
        int k = idx / n4row;
        int n = (idx - k * n4row) * 4;
        int which = n >> 10, h = (n >> 6) & 15, d = n & 63;
        const float* W = (which == 0) ? Wq : (which == 1) ? Wk : Wv;
        float4 v = *(const float4*)&W[((size_t)h * C_ + k) * HS + d];
        v.x = tf32r(v.x); v.y = tf32r(v.y); v.z = tf32r(v.z); v.w = tf32r(v.w);
        *(float4*)&wqkv[(size_t)k * (3 * C_) + n] = v;
        return;
    }
    idx -= NQ;
    const float* src; float* dst;
    if (idx < NO)            { src = Wo; dst = wo; }
    else if ((idx -= NO) < N1) { src = W1; dst = w1; }
    else                     { idx -= N1; src = W2; dst = w2; }
    float4 v = ((const float4*)src)[idx];
    v.x = tf32r(v.x); v.y = tf32r(v.y); v.z = tf32r(v.z); v.w = tf32r(v.w);
    ((float4*)dst)[idx] = v;
}

// ======================= LayerNorm =========================================
__global__ void ln_kernel(const float* __restrict__ x,
                          const float* __restrict__ g,
                          const float* __restrict__ b,
                          float* __restrict__ out) {
    int row = blockIdx.x;
    int tid = threadIdx.x;
    const float4* xr = (const float4*)(x + (size_t)row * C_);
    float4 xv = xr[tid];
    float s  = xv.x + xv.y + xv.z + xv.w;
    float ss = xv.x * xv.x + xv.y * xv.y + xv.z * xv.z + xv.w * xv.w;
    #pragma unroll
    for (int o = 16; o > 0; o >>= 1) {
        s  += __shfl_xor_sync(0xffffffffu, s,  o);
        ss += __shfl_xor_sync(0xffffffffu, ss, o);
    }
    __shared__ float sb[8], sb2[8];
    int wid = tid >> 5, lid = tid & 31;
    if (lid == 0) { sb[wid] = s; sb2[wid] = ss; }
    __syncthreads();
    float tot = 0.f, tot2 = 0.f;
    #pragma unroll
    for (int i = 0; i < 8; i++) { tot += sb[i]; tot2 += sb2[i]; }
    float mean = tot * (1.0f / C_);
    float var  = tot2 * (1.0f / C_) - mean * mean;
    float rstd = rsqrtf(var + 1e-5f);
    float4 gv = ((const float4*)g)[tid];
    float4 bv = ((const float4*)b)[tid];
    float4 ov;
    ov.x = tf32r((xv.x - mean) * rstd * gv.x + bv.x);
    ov.y = tf32r((xv.y - mean) * rstd * gv.y + bv.y);
    ov.z = tf32r((xv.z - mean) * rstd * gv.z + bv.z);
    ov.w = tf32r((xv.w - mean) * rstd * gv.w + bv.w);
    ((float4*)(out + (size_t)row * C_))[tid] = ov;
}

// ======================= TF32 mma.sync GEMM ================================
// CTA tile 128x256, BK=32, 8 warps (2M x 4N), warp tile 64x64.
// 3-stage cp.async pipeline + double-buffered register fragments.
static constexpr int BM = 128, BN = 256, BK = 32;
static constexpr int APAD = 36;
static constexpr int BPAD = 264;
static constexpr int ABYTES = BM * APAD * 4;
static constexpr int BBYTES = BK * BPAD * 4;
static constexpr int STAGE_BYTES = ABYTES + BBYTES;
static constexpr int NSTAGES = 3;
static constexpr int MM_SMEM = NSTAGES * STAGE_BYTES;

template<int EPI>
__global__ __launch_bounds__(256, 1)
void mm_kernel(const float* __restrict__ A, const float* __restrict__ Bw,
               const float* __restrict__ bias, const float* __restrict__ res,
               float* __restrict__ Cout, int K, int N) {
    extern __shared__ __align__(16) char dsm[];
    const uint32_t smem0 = smem_u32(dsm);
    const int tid  = threadIdx.x;
    const int wid  = tid >> 5;
    const int lane = tid & 31;
    const int m0 = blockIdx.y * BM;
    const int n0 = blockIdx.x * BN;
    const int nch = K >> 5;

    const int warpM = wid >> 2;
    const int warpN = wid & 3;

    const int arow0 = tid >> 3;
    const int acb   = (tid & 7) << 4;
    const int brow  = tid >> 3;
    const int bc0   = (tid & 7) << 4;

    float acc[4][8][4];
    #pragma unroll
    for (int mt = 0; mt < 4; mt++)
        #pragma unroll
        for (int nt = 0; nt < 8; nt++)
            #pragma unroll
            for (int r = 0; r < 4; r++) acc[mt][nt][r] = 0.f;

    auto load_stage = [&](int st, int kpos) {
        uint32_t sa  = smem0 + st * STAGE_BYTES;
        uint32_t sbm = sa + ABYTES;
        #pragma unroll
        for (int j = 0; j < 4; j++) {
            int r = arow0 + j * 32;
            cp16(sa + r * (APAD * 4) + acb,
                 A + (size_t)(m0 + r) * K + kpos + (acb >> 2));
        }
        const float* brp = Bw + (size_t)(kpos + brow) * N + n0;
        #pragma unroll
        for (int j = 0; j < 8; j++) {
            int cb = bc0 + j * 128;
            cp16(sbm + brow * (BPAD * 4) + cb, brp + (cb >> 2));
        }
    };

    load_stage(0, 0); CP_COMMIT();
    load_stage(1, 32); CP_COMMIT();

    const int fr = lane >> 2;
    const int fc = lane & 3;

    uint32_t afr[2][4][4];
    uint32_t bfr[2][8][2];

    auto load_frags = [&](const float* Asm, const float* Bsm, int kk, int buf) {
        const int km = kk * 8 + fc;
        #pragma unroll
        for (int mt = 0; mt < 4; mt++) {
            const int mr = warpM * 64 + mt * 16 + fr;
            afr[buf][mt][0] = __float_as_uint(Asm[mr * APAD + km]);
            afr[buf][mt][1] = __float_as_uint(Asm[(mr + 8) * APAD + km]);
            afr[buf][mt][2] = __float_as_uint(Asm[mr * APAD + km + 4]);
            afr[buf][mt][3] = __float_as_uint(Asm[(mr + 8) * APAD + km + 4]);
        }
        #pragma unroll
        for (int nt = 0; nt < 8; nt++) {
            const int nc = warpN * 64 + nt * 8 + fr;
            bfr[buf][nt][0] = __float_as_uint(Bsm[km * BPAD + nc]);
            bfr[buf][nt][1] = __float_as_uint(Bsm[(km + 4) * BPAD + nc]);
        }
    };

    for (int kc = 0; kc < nch; kc++) {
        CP_WAIT1();
        __syncthreads();
        if (kc + 2 < nch) load_stage((kc + 2) % NSTAGES, (kc + 2) * 32);
        CP_COMMIT();

        const float* Asm = (const float*)(dsm + (kc % NSTAGES) * STAGE_BYTES);
        const float* Bsm = (const float*)((const char*)Asm + ABYTES);

        load_frags(Asm, Bsm, 0, 0);
        #pragma unroll
        for (int kk = 0; kk < 4; kk++) {
            const int cur = kk & 1;
            if (kk < 3) load_frags(Asm, Bsm, kk + 1, cur ^ 1);
            #pragma unroll
            for (int mt = 0; mt < 4; mt++)
                #pragma unroll
                for (int nt = 0; nt < 8; nt++)
                    mma_tf32(acc[mt][nt], afr[cur][mt], bfr[cur][nt]);
        }
    }

    // ---------------- epilogue ----------------
    #pragma unroll
    for (int mt = 0; mt < 4; mt++) {
        #pragma unroll
        for (int half = 0; half < 2; half++) {
            const int m = m0 + warpM * 64 + mt * 16 + fr + half * 8;
            #pragma unroll
            for (int nt = 0; nt < 8; nt++) {
                const int n = n0 + warpN * 64 + nt * 8 + 2 * fc;
                float2 v = make_float2(acc[mt][nt][half * 2], acc[mt][nt][half * 2 + 1]);
                if (EPI == 0) {
                    v.x = tf32r(v.x); v.y = tf32r(v.y);
                    const int b = m >> 11, t = m & 2047;
                    const int which = n >> 10, h = (n >> 6) & 15, d = n & 63;
                    *(float2*)&Cout[((((size_t)which * B_ + b) * H_ + h) * T_ + t) * HS + d] = v;
                } else {
                    const float2 bb = *(const float2*)&bias[n];
                    v.x += bb.x; v.y += bb.y;
                    if (EPI == 1) {
                        float2 rr = *(const float2*)&res[(size_t)m * N + n];
                        v.x += rr.x; v.y += rr.y;
                    } else {
                        v.x = tf32r(fmaxf(v.x, 0.f));
                        v.y = tf32r(fmaxf(v.y, 0.f));
                    }
                    *(float2*)&Cout[(size_t)m * N + n] = v;
                }
            }
        }
    }
}

// ======================= tensor-core causal flash attention ================
static constexpr int KP = 68;
static constexpr int VP = 72;
static constexpr int PP = 68;
static constexpr int KS_FL = 64 * KP;
static constexpr int VS_FL = 64 * VP;
static constexpr int AT_SMEM = (2 * KS_FL + 2 * VS_FL + 128 * PP) * 4;

__global__ __launch_bounds__(256, 1)
void attn_kernel(const float* __restrict__ Q,
                 const float* __restrict__ K,
                 const float* __restrict__ V,
                 float* __restrict__ out) {
    const int bh = blockIdx.y;
    const int q0 = ((int)gridDim.x - 1 - (int)blockIdx.x) * 128;
    const int tid = threadIdx.x, w = tid >> 5, lane = tid & 31;
    const int qw = q0 + w * 16;
    const int r = lane >> 2, c = lane & 3;

    extern __shared__ __align__(16) float sm[];
    float* Ksm = sm;
    float* Vsm = sm + 2 * KS_FL;
    float* Ps  = sm + 2 * KS_FL + 2 * VS_FL;

    const float* Kbh = K + (size_t)bh * T_ * HS;
    const float* Vbh = V + (size_t)bh * T_ * HS;

    {
        const float4* qp = (const float4*)(Q + ((size_t)bh * T_ + q0) * HS);
        for (int i = tid; i < 128 * 16; i += 256) {
            int row = i >> 4, c4 = i & 15;
            *(float4*)&Ps[row * PP + c4 * 4] = qp[i];
        }
    }
    __syncthreads();
    float a_q[8][4];
    #pragma unroll
    for (int kc = 0; kc < 8; kc++) {
        const float* base = &Ps[(w * 16 + r) * PP + kc * 8 + c];
        a_q[kc][0] = base[0] * 0.125f;
        a_q[kc][1] = base[8 * PP] * 0.125f;
        a_q[kc][2] = base[4] * 0.125f;
        a_q[kc][3] = base[8 * PP + 4] * 0.125f;
    }

    auto load_kv = [&](int tile, int st) {
        const float4* kp = (const float4*)(Kbh + (size_t)(tile * 64) * HS);
        const float4* vp = (const float4*)(Vbh + (size_t)(tile * 64) * HS);
        float* kd = Ksm + st * KS_FL;
        float* vd = Vsm + st * VS_FL;
        for (int i = tid; i < 64 * 16; i += 256) {
            int row = i >> 4, c4 = i & 15;
            cp16(smem_u32(&kd[row * KP + c4 * 4]), &kp[i]);
            cp16(smem_u32(&vd[row * VP + c4 * 4]), &vp[i]);
        }
    };

    const int ntiles = (q0 + 128) >> 6;
    load_kv(0, 0); CP_COMMIT();

    float o[8][4];
    #pragma unroll
    for (int nt = 0; nt < 8; nt++)
        #pragma unroll
        for (int j = 0; j < 4; j++) o[nt][j] = 0.f;
    float m0 = -1e30f, m1 = -1e30f, l0 = 0.f, l1 = 0.f;

    for (int t = 0; t < ntiles; t++) {
        __syncthreads();
        if (t + 1 < ntiles) { load_kv(t + 1, (t + 1) & 1); CP_COMMIT(); CP_WAIT1(); }
        else CP_WAIT0();
        __syncthreads();

        const int k0 = t * 64;
        if (k0 > qw + 15) continue;
        const float* Kst = Ksm + (t & 1) * KS_FL;
        const float* Vst = Vsm + (t & 1) * VS_FL;

        // ---- S = Q @ K^T (double-buffered K fragments) ----
        float s[8][4];
        #pragma unroll
        for (int nt = 0; nt < 8; nt++)
            #pragma unroll
            for (int j = 0; j < 4; j++) s[nt][j] = 0.f;
        uint32_t kf[2][8][2];
        #pragma unroll
        for (int nt = 0; nt < 8; nt++) {
            kf[0][nt][0] = __float_as_uint(Kst[(nt * 8 + r) * KP + c]);
            kf[0][nt][1] = __float_as_uint(Kst[(nt * 8 + r) * KP + c + 4]);
        }
        #pragma unroll
        for (int kc = 0; kc < 8; kc++) {
            const int cur = kc & 1;
            if (kc < 7) {
                const int km = (kc + 1) * 8 + c;
                #pragma unroll
                for (int nt = 0; nt < 8; nt++) {
                    kf[cur ^ 1][nt][0] = __float_as_uint(Kst[(nt * 8 + r) * KP + km]);
                    kf[cur ^ 1][nt][1] = __float_as_uint(Kst[(nt * 8 + r) * KP + km + 4]);
                }
            }
            const uint32_t* aq = (const uint32_t*)a_q[kc];
            #pragma unroll
            for (int nt = 0; nt < 8; nt++)
                mma_tf32(s[nt], aq, kf[cur][nt]);
        }

        if (k0 + 63 > qw) {
            const int row0 = qw + r, row1 = qw + r + 8;
            #pragma unroll
            for (int nt = 0; nt < 8; nt++) {
                const int key = k0 + nt * 8 + 2 * c;
                if (key     > row0) s[nt][0] = -1e30f;
                if (key + 1 > row0) s[nt][1] = -1e30f;
                if (key     > row1) s[nt][2] = -1e30f;
                if (key + 1 > row1) s[nt][3] = -1e30f;
            }
        }

        float mx0 = m0, mx1 = m1;
        #pragma unroll
        for (int nt = 0; nt < 8; nt++) {
            mx0 = fmaxf(mx0, fmaxf(s[nt][0], s[nt][1]));
            mx1 = fmaxf(mx1, fmaxf(s[nt][2], s[nt][3]));
        }
        mx0 = fmaxf(mx0, __shfl_xor_sync(0xffffffffu, mx0, 1));
        mx0 = fmaxf(mx0, __shfl_xor_sync(0xffffffffu, mx0, 2));
        mx1 = fmaxf(mx1, __shfl_xor_sync(0xffffffffu, mx1, 1));
        mx1 = fmaxf(mx1, __shfl_xor_sync(0xffffffffu, mx1, 2));
        const float corr0 = __expf(m0 - mx0);
        const float corr1 = __expf(m1 - mx1);
        m0 = mx0; m1 = mx1;

        __syncwarp();
        float ls0 = 0.f, ls1 = 0.f;
        float* prow0 = &Ps[(w * 16 + r) * PP];
        float* prow1 = &Ps[(w * 16 + r + 8) * PP];
        #pragma unroll
        for (int nt = 0; nt < 8; nt++) {
            float p0 = tf32r(__expf(s[nt][0] - mx0));
            float p1 = tf32r(__expf(s[nt][1] - mx0));
            float p2 = tf32r(__expf(s[nt][2] - mx1));
            float p3 = tf32r(__expf(s[nt][3] - mx1));
            ls0 += p0 + p1; ls1 += p2 + p3;
            *(float2*)&prow0[nt * 8 + 2 * c] = make_float2(p0, p1);
            *(float2*)&prow1[nt * 8 + 2 * c] = make_float2(p2, p3);
        }
        ls0 += __shfl_xor_sync(0xffffffffu, ls0, 1);
        ls0 += __shfl_xor_sync(0xffffffffu, ls0, 2);
        ls1 += __shfl_xor_sync(0xffffffffu, ls1, 1);
        ls1 += __shfl_xor_sync(0xffffffffu, ls1, 2);
        l0 = l0 * corr0 + ls0;
        l1 = l1 * corr1 + ls1;

        #pragma unroll
        for (int nt = 0; nt < 8; nt++) {
            o[nt][0] *= corr0; o[nt][1] *= corr0;
            o[nt][2] *= corr1; o[nt][3] *= corr1;
        }
        __syncwarp();

        // ---- O += P @ V (double-buffered fragments) ----
        uint32_t pf[2][4], vf[2][8][2];
        {
            pf[0][0] = __float_as_uint(Ps[(w * 16 + r) * PP + c]);
            pf[0][1] = __float_as_uint(Ps[(w * 16 + r + 8) * PP + c]);
            pf[0][2] = __float_as_uint(Ps[(w * 16 + r) * PP + c + 4]);
            pf[0][3] = __float_as_uint(Ps[(w * 16 + r + 8) * PP + c + 4]);
            #pragma unroll
            for (int nt = 0; nt < 8; nt++) {
                vf[0][nt][0] = __float_as_uint(Vst[c * VP + nt * 8 + r]);
                vf[0][nt][1] = __float_as_uint(Vst[(c + 4) * VP + nt * 8 + r]);
            }
        }
        #pragma unroll
        for (int kc = 0; kc < 8; kc++) {
            const int cur = kc & 1;
            if (kc < 7) {
                const int km = (kc + 1) * 8;
                pf[cur ^ 1][0] = __float_as_uint(Ps[(w * 16 + r) * PP + km + c]);
                pf[cur ^ 1][1] = __float_as_uint(Ps[(w * 16 + r + 8) * PP + km + c]);
                pf[cur ^ 1][2] = __float_as_uint(Ps[(w * 16 + r) * PP + km + c + 4]);
                pf[cur ^ 1][3] = __float_as_uint(Ps[(w * 16 + r + 8) * PP + km + c + 4]);
                #pragma unroll
                for (int nt = 0; nt < 8; nt++) {
                    vf[cur ^ 1][nt][0] = __float_as_uint(Vst[(km + c) * VP + nt * 8 + r]);
                    vf[cur ^ 1][nt][1] = __float_as_uint(Vst[(km + c + 4) * VP + nt * 8 + r]);
                }
            }
            #pragma unroll
            for (int nt = 0; nt < 8; nt++)
                mma_tf32(o[nt], pf[cur], vf[cur][nt]);
        }
    }

    const float inv0 = 1.0f / l0, inv1 = 1.0f / l1;
    const int b = bh >> 4, h = bh & 15;
    float* ob0 = out + ((size_t)(b * T_ + qw + r)) * C_ + h * HS;
    float* ob1 = out + ((size_t)(b * T_ + qw + r + 8)) * C_ + h * HS;
    #pragma unroll
    for (int nt = 0; nt < 8; nt++) {
        *(float2*)&ob0[nt * 8 + 2 * c] =
            make_float2(tf32r(o[nt][0] * inv0), tf32r(o[nt][1] * inv0));
        *(float2*)&ob1[nt * 8 + 2 * c] =
            make_float2(tf32r(o[nt][2] * inv1), tf32r(o[nt][3] * inv1));
    }
}

// ===========================================================================
extern "C" void kernel_launch(void* const* d_in, const int* in_sizes, int n_in,
                              void* d_out, int out_size) {
    const float* x   = (const float*)d_in[0];
    const float* Wq  = (const float*)d_in[1];
    const float* Wk  = (const float*)d_in[2];
    const float* Wv  = (const float*)d_in[3];
    const float* Wo  = (const float*)d_in[4];
    const float* bo  = (const float*)d_in[5];
    const float* g1  = (const float*)d_in[6];
    const float* be1 = (const float*)d_in[7];
    const float* g2  = (const float*)d_in[8];
    const float* be2 = (const float*)d_in[9];
    const float* W1  = (const float*)d_in[10];
    const float* b1  = (const float*)d_in[11];
    const float* W2  = (const float*)d_in[12];
    const float* b2  = (const float*)d_in[13];
    float* out = (float*)d_out;

    float *xn, *qkv, *att, *x1, *xn2, *h, *wqkv, *wo, *w1, *w2;
    cudaGetSymbolAddress((void**)&xn,   g_xn);
    cudaGetSymbolAddress((void**)&qkv,  g_qkv);
    cudaGetSymbolAddress((void**)&att,  g_att);
    cudaGetSymbolAddress((void**)&x1,   g_x1);
    cudaGetSymbolAddress((void**)&xn2,  g_xn2);
    cudaGetSymbolAddress((void**)&h,    g_h);
    cudaGetSymbolAddress((void**)&wqkv, g_wqkv);
    cudaGetSymbolAddress((void**)&wo,   g_wo);
    cudaGetSymbolAddress((void**)&w1,   g_w1);
    cudaGetSymbolAddress((void**)&w2,   g_w2);

    cudaFuncSetAttribute(mm_kernel<0>, cudaFuncAttributeMaxDynamicSharedMemorySize, MM_SMEM);
    cudaFuncSetAttribute(mm_kernel<1>, cudaFuncAttributeMaxDynamicSharedMemorySize, MM_SMEM);
    cudaFuncSetAttribute(mm_kernel<2>, cudaFuncAttributeMaxDynamicSharedMemorySize, MM_SMEM);
    cudaFuncSetAttribute(attn_kernel,  cudaFuncAttributeMaxDynamicSharedMemorySize, AT_SMEM);

    // fused weight prep: 3145728 float4 total
    prep_kernel<<<(3 * C_ * C_ + C_ * C_ + 2 * C_ * FF) / 4 / 256, 256>>>(
        Wq, Wk, Wv, Wo, W1, W2, wqkv, wo, w1, w2);

    // 1) ln1
    ln_kernel<<<BT, 256>>>(x, g1, be1, xn);
    // 2) fused QKV GEMM -> scatter [3,B,H,T,hs]
    mm_kernel<0><<<dim3(3 * C_ / BN, BT / BM), 256, MM_SMEM>>>(xn, wqkv, nullptr, nullptr, qkv, C_, 3 * C_);
    // 3) tensor-core flash attention
    attn_kernel<<<dim3(T_ / 128, B_ * H_), 256, AT_SMEM>>>(
        qkv, qkv + (size_t)BT * C_, qkv + 2 * (size_t)BT * C_, att);
    // 4) x1 = x + att @ Wo + bo
    mm_kernel<1><<<dim3(C_ / BN, BT / BM), 256, MM_SMEM>>>(att, wo, bo, x, x1, C_, C_);
    // 5) ln2
    ln_kernel<<<BT, 256>>>(x1, g2, be2, xn2);
    // 6) h = relu(xn2 @ W1 + b1)
    mm_kernel<2><<<dim3(FF / BN, BT / BM), 256, MM_SMEM>>>(xn2, w1, b1, nullptr, h, C_, FF);
    // 7) out = x1 + h @ W2 + b2
    mm_kernel<1><<<dim3(C_ / BN, BT / BM), 256, MM_SMEM>>>(h, w2, b2, x1, out, FF, C_);
}